// round 9
// baseline (speedup 1.0000x reference)
#include <cuda_runtime.h>
#include <cuda_bf16.h>
#include <cstdint>
#include <math.h>

#define Hh 12
#define Dd 768
#define T1c 512
#define T2c 64
#define Bb 16
#define SPAD 68

static const float PROJ_SCALE = 0.3535533905932738f; // 64^-0.25
#define NEGBIG (-1e9f)

// ======================= PTX helpers (baseline ISA only) ====================
__device__ __forceinline__ uint32_t smem_to_u32(const void* p) {
    uint32_t a;
    asm("{ .reg .u64 t; cvta.to.shared.u64 t, %1; cvt.u32.u64 %0, t; }" : "=r"(a) : "l"(p));
    return a;
}
__device__ __forceinline__ void cp16(uint32_t saddr, const void* g) {
    asm volatile("cp.async.ca.shared.global [%0], [%1], 16;" :: "r"(saddr), "l"(g));
}
__device__ __forceinline__ void ldsm4(uint32_t* r, uint32_t addr) {
    asm volatile("ldmatrix.sync.aligned.m8n8.x4.shared.b16 {%0,%1,%2,%3}, [%4];"
        : "=r"(r[0]), "=r"(r[1]), "=r"(r[2]), "=r"(r[3]) : "r"(addr));
}
__device__ __forceinline__ void mma_bf16(float* c, const uint32_t* a, const uint32_t* b) {
    asm volatile(
        "mma.sync.aligned.m16n8k16.row.col.f32.bf16.bf16.f32 "
        "{%0,%1,%2,%3}, {%4,%5,%6,%7}, {%8,%9}, {%0,%1,%2,%3};"
        : "+f"(c[0]), "+f"(c[1]), "+f"(c[2]), "+f"(c[3])
        : "r"(a[0]), "r"(a[1]), "r"(a[2]), "r"(a[3]), "r"(b[0]), "r"(b[1]));
}

// ======================= scratch (device globals) ===========================
__device__ float g_proj_f[6ull * Bb * T1c * Dd];   // [6][B][H][T1][64]
__device__ float g_proj_i[6ull * Bb * T2c * Dd];   // [6][B][H][T2][64]

__device__ __nv_bfloat16 g_fh[(size_t)Bb * T1c * Dd], g_fl[(size_t)Bb * T1c * Dd];
__device__ __nv_bfloat16 g_ih[(size_t)Bb * T2c * Dd], g_il[(size_t)Bb * T2c * Dd];
// all 14 weight matrices in one hi/lo pair: [0..5]=W_f, [6..11]=W_i, [12]=Wu_v, [13]=Wu_l
__device__ __nv_bfloat16 g_wh[14ull * Dd * Dd], g_wl[14ull * Dd * Dd];
__device__ __nv_bfloat16 g_avh[(size_t)Bb * T1c * Dd], g_avl[(size_t)Bb * T1c * Dd];
__device__ __nv_bfloat16 g_alh[(size_t)Bb * T2c * Dd], g_all[(size_t)Bb * T2c * Dd];

// ======================= conversion kernels =================================
__global__ __launch_bounds__(256) void conv_split(
    const float* __restrict__ x, __nv_bfloat16* __restrict__ hi,
    __nv_bfloat16* __restrict__ lo, int n)
{
    int i = blockIdx.x * 256 + threadIdx.x;
    if (i < n) {
        float v = x[i];
        __nv_bfloat16 h = __float2bfloat16(v);
        hi[i] = h;
        lo[i] = __float2bfloat16(v - __bfloat162float(h));
    }
}

// All 14 weight matrices [K=768][N=768] -> [z][N][K] hi/lo in one launch.
__global__ __launch_bounds__(256) void conv_wsplit_all(
    const float* __restrict__ W_f, const float* __restrict__ W_i,
    const float* __restrict__ Wu_v, const float* __restrict__ Wu_l,
    __nv_bfloat16* __restrict__ bh, __nv_bfloat16* __restrict__ bl)
{
    __shared__ float t[32][33];
    const int z = blockIdx.z;
    const float* Wz;
    if (z < 6)       Wz = W_f  + (size_t)z * Dd * Dd;
    else if (z < 12) Wz = W_i  + (size_t)(z - 6) * Dd * Dd;
    else if (z == 12) Wz = Wu_v;
    else             Wz = Wu_l;
    const int k0 = blockIdx.y * 32, n0 = blockIdx.x * 32;
    const int tx = threadIdx.x & 31, ty = threadIdx.x >> 5; // 32 x 8
#pragma unroll
    for (int j = 0; j < 32; j += 8)
        t[ty + j][tx] = Wz[(size_t)(k0 + ty + j) * Dd + n0 + tx];
    __syncthreads();
#pragma unroll
    for (int j = 0; j < 32; j += 8) {
        float v = t[tx][ty + j];  // = W[k0+tx][n0+ty+j]
        size_t o = (size_t)z * Dd * Dd + (size_t)(n0 + ty + j) * Dd + k0 + tx;
        __nv_bfloat16 h = __float2bfloat16(v);
        bh[o] = h;
        bl[o] = __float2bfloat16(v - __bfloat162float(h));
    }
}

// ======================= mma.sync split-bf16 GEMM (unchanged) ===============
#define ROWB 80                 // 32 bf16 + 8 pad = 40 elems = 80 bytes/row
#define TILE_B (128 * ROWB)     // 10240
#define STAGE_B (4 * TILE_B)    // 40960: [Ah | Al | Bh | Bl]
#define GEMM_SMEM (2 * STAGE_B) // 81920

__global__ __launch_bounds__(256, 2) void gemm_mma(
    const __nv_bfloat16* __restrict__ Ah, const __nv_bfloat16* __restrict__ Al,
    const __nv_bfloat16* __restrict__ Bh, const __nv_bfloat16* __restrict__ Bl,
    const float* __restrict__ biasbase, float* __restrict__ Cbase,
    int M, int T, float scale, int mode)
{
    extern __shared__ __align__(16) char smem[];
    const uint32_t sb = smem_to_u32(smem);
    const int tid = threadIdx.x, lane = tid & 31, wid = tid >> 5;
    const int wm = wid & 1, wn = wid >> 1;
    const int z = blockIdx.z;
    const int m0 = blockIdx.y * 128, n0 = blockIdx.x * 128;

    const __nv_bfloat16* srcs[4];
    srcs[0] = Ah; srcs[1] = Al;
    srcs[2] = Bh + (size_t)z * Dd * Dd; srcs[3] = Bl + (size_t)z * Dd * Dd;

    float acc[4][4][4];
#pragma unroll
    for (int a = 0; a < 4; a++)
#pragma unroll
        for (int b = 0; b < 4; b++)
#pragma unroll
            for (int c = 0; c < 4; c++) acc[a][b][c] = 0.0f;

#define LOAD_STAGE(kc, s) do {                                                \
    _Pragma("unroll")                                                         \
    for (int t_ = 0; t_ < 4; t_++) {                                          \
        const __nv_bfloat16* src_ = srcs[t_];                                 \
        const int rowbase_ = (t_ < 2) ? m0 : n0;                              \
        _Pragma("unroll")                                                     \
        for (int u_ = 0; u_ < 2; u_++) {                                      \
            const int idx_ = tid * 2 + u_;                                    \
            const int row_ = idx_ >> 2, cc_ = idx_ & 3;                       \
            cp16(sb + (s) * STAGE_B + t_ * TILE_B + row_ * ROWB + cc_ * 16,   \
                 src_ + (size_t)(rowbase_ + row_) * Dd + (kc) * 32 + cc_ * 8);\
        }                                                                     \
    }                                                                         \
    asm volatile("cp.async.commit_group;" ::: "memory");                      \
} while (0)

    LOAD_STAGE(0, 0);

    for (int i = 0; i < 24; i++) {
        const int s = i & 1;
        if (i + 1 < 24) {
            LOAD_STAGE(i + 1, s ^ 1);
            asm volatile("cp.async.wait_group 1;" ::: "memory");
        } else {
            asm volatile("cp.async.wait_group 0;" ::: "memory");
        }
        __syncthreads();

        const uint32_t st = sb + s * STAGE_B;
#pragma unroll
        for (int ks = 0; ks < 2; ks++) {
            const int kb = ks * 32;   // byte offset along K within the row
            uint32_t bh[4][2], bl[4][2];
#pragma unroll
            for (int p = 0; p < 2; p++) {
                uint32_t r[4];
                uint32_t ab = st + 2 * TILE_B +
                              (wn * 32 + p * 16 + (lane & 15)) * ROWB +
                              ((lane >> 4) * 16) + kb;
                ldsm4(r, ab);                      // non-trans: [n][k] == col-major kxn
                bh[p * 2][0] = r[0]; bh[p * 2 + 1][0] = r[1];
                bh[p * 2][1] = r[2]; bh[p * 2 + 1][1] = r[3];
                ldsm4(r, ab + TILE_B);
                bl[p * 2][0] = r[0]; bl[p * 2 + 1][0] = r[1];
                bl[p * 2][1] = r[2]; bl[p * 2 + 1][1] = r[3];
            }
            uint32_t a[4][4];
#pragma unroll
            for (int mt = 0; mt < 4; mt++)
                ldsm4(a[mt], st + (wm * 64 + mt * 16 + (lane & 15)) * ROWB +
                             ((lane >> 4) * 16) + kb);
#pragma unroll
            for (int mt = 0; mt < 4; mt++)
#pragma unroll
                for (int nt = 0; nt < 4; nt++) {
                    mma_bf16(acc[mt][nt], a[mt], bh[nt]);
                    mma_bf16(acc[mt][nt], a[mt], bl[nt]);
                }
#pragma unroll
            for (int mt = 0; mt < 4; mt++)
                ldsm4(a[mt], st + TILE_B + (wm * 64 + mt * 16 + (lane & 15)) * ROWB +
                             ((lane >> 4) * 16) + kb);
#pragma unroll
            for (int mt = 0; mt < 4; mt++)
#pragma unroll
                for (int nt = 0; nt < 4; nt++)
                    mma_bf16(acc[mt][nt], a[mt], bh[nt]);
        }
        __syncthreads();
    }

    // epilogue: fragment -> global (float2 stores)
    const float* bias = biasbase + (size_t)z * Dd;
    float* C = Cbase + (size_t)z * M * Dd;
#pragma unroll
    for (int mt = 0; mt < 4; mt++)
#pragma unroll
        for (int nt = 0; nt < 4; nt++) {
            const int n = n0 + wn * 32 + nt * 8 + (lane & 3) * 2;
            const float2 bv = *(const float2*)&bias[n];
#pragma unroll
            for (int hf = 0; hf < 2; hf++) {
                const int m = m0 + wm * 64 + mt * 16 + (lane >> 2) + hf * 8;
                float2 v;
                v.x = scale * (acc[mt][nt][hf * 2 + 0] + bv.x);
                v.y = scale * (acc[mt][nt][hf * 2 + 1] + bv.y);
                if (mode == 0) {
                    const int b_ = m / T, t_ = m - b_ * T;
                    const int h = n >> 6, e = n & 63;
                    *(float2*)&C[((((size_t)(b_ * Hh + h)) * T + t_) << 6) + e] = v;
                } else {
                    *(float2*)&C[(size_t)m * Dd + n] = v;
                }
            }
        }
}

// ======================= flash attention (bf16 hi/lo epilogue) ===============
__global__ __launch_bounds__(256) void flash_kernel(
    const float* __restrict__ Q1,
    const float* __restrict__ Q2,
    const float* __restrict__ K1,
    const float* __restrict__ V1,
    const float* __restrict__ K2,
    const float* __restrict__ V2,
    const int* __restrict__ mask,
    __nv_bfloat16* __restrict__ outh,
    __nv_bfloat16* __restrict__ outl,
    int Tq)
{
    extern __shared__ __align__(16) float sm[];
    float* Qs   = sm;
    float* Ks   = Qs + 64 * SPAD;
    float* Vs   = Ks + 64 * SPAD;
    float* Ss   = Vs + 64 * 64;
    float* m_s  = Ss + 64 * SPAD;
    float* l_s  = m_s + 64;
    float* corr = l_s + 64;
    float* mflag = corr + 64;

    const int tid = threadIdx.x;
    const int tx = tid & 15;
    const int ty = tid >> 4;
    const int b = blockIdx.z, h = blockIdx.y, qt = blockIdx.x;

    const float* Q1p = Q1 + (((size_t)(b * Hh + h) * Tq) + qt * 64) * 64;
    const float* Q2p = Q2 + (((size_t)(b * Hh + h) * Tq) + qt * 64) * 64;
    const float* K1p = K1 + ((size_t)(b * Hh + h) * T1c) * 64;
    const float* V1p = V1 + ((size_t)(b * Hh + h) * T1c) * 64;
    const float* K2p = K2 + ((size_t)(b * Hh + h) * T2c) * 64;
    const float* V2p = V2 + ((size_t)(b * Hh + h) * T2c) * 64;

    for (int i = tid; i < 64 * 64; i += 256) {
        const int r = i >> 6, e = i & 63;
        Qs[e * SPAD + r] = Q1p[i];
    }
    for (int j = tid; j < T1c + T2c; j += 256)
        mflag[j] = (mask[b * (T1c + T2c) + j] != 0) ? 1.0f : 0.0f;
    if (tid < 64) { m_s[tid] = -1e30f; l_s[tid] = 0.0f; }

    float acc[4][4];
#pragma unroll
    for (int i = 0; i < 4; i++)
#pragma unroll
        for (int j = 0; j < 4; j++) acc[i][j] = 0.0f;

    for (int kt = 0; kt < 9; kt++) {
        const float* Kt;
        const float* Vt;
        int koff;
        if (kt < 8) { Kt = K1p + kt * 64 * 64; Vt = V1p + kt * 64 * 64; koff = kt * 64; }
        else        { Kt = K2p;               Vt = V2p;               koff = T1c; }

        __syncthreads();
        if (kt == 8) {
            for (int i = tid; i < 64 * 64; i += 256) {
                const int r = i >> 6, e = i & 63;
                Qs[e * SPAD + r] = Q2p[i];
            }
        }
        for (int i = tid; i < 64 * 64; i += 256) {
            const int j = i >> 6, e = i & 63;
            Ks[e * SPAD + j] = Kt[i];
        }
        for (int i = tid * 4; i < 64 * 64; i += 256 * 4)
            *(float4*)&Vs[i] = *(const float4*)&Vt[i];
        __syncthreads();

        float s[4][4];
#pragma unroll
        for (int i = 0; i < 4; i++)
#pragma unroll
            for (int j = 0; j < 4; j++) s[i][j] = 0.0f;
#pragma unroll 8
        for (int e = 0; e < 64; e++) {
            const float4 q  = *(const float4*)&Qs[e * SPAD + tx * 4];
            const float4 kv = *(const float4*)&Ks[e * SPAD + ty * 4];
            const float qa[4] = {q.x, q.y, q.z, q.w};
            const float ka[4] = {kv.x, kv.y, kv.z, kv.w};
#pragma unroll
            for (int i = 0; i < 4; i++)
#pragma unroll
                for (int j = 0; j < 4; j++)
                    s[i][j] += qa[i] * ka[j];
        }
#pragma unroll
        for (int jj = 0; jj < 4; jj++) {
            const float mf = mflag[koff + ty * 4 + jj];
            float4 v;
            v.x = (mf != 0.0f) ? NEGBIG : s[0][jj];
            v.y = (mf != 0.0f) ? NEGBIG : s[1][jj];
            v.z = (mf != 0.0f) ? NEGBIG : s[2][jj];
            v.w = (mf != 0.0f) ? NEGBIG : s[3][jj];
            *(float4*)&Ss[(ty * 4 + jj) * SPAD + tx * 4] = v;
        }
        __syncthreads();

        if (tid < 64) {
            const float mold = m_s[tid];
            float mx = mold;
            for (int j = 0; j < 64; j++) mx = fmaxf(mx, Ss[j * SPAD + tid]);
            const float c = __expf(mold - mx);
            float sum = 0.0f;
            for (int j = 0; j < 64; j++) {
                const float p = __expf(Ss[j * SPAD + tid] - mx);
                Ss[j * SPAD + tid] = p;
                sum += p;
            }
            l_s[tid] = l_s[tid] * c + sum;
            m_s[tid] = mx;
            corr[tid] = c;
        }
        __syncthreads();

        const float c0 = corr[tx * 4 + 0];
        const float c1 = corr[tx * 4 + 1];
        const float c2 = corr[tx * 4 + 2];
        const float c3 = corr[tx * 4 + 3];
#pragma unroll
        for (int j = 0; j < 4; j++) {
            acc[0][j] *= c0; acc[1][j] *= c1; acc[2][j] *= c2; acc[3][j] *= c3;
        }
#pragma unroll 8
        for (int kk = 0; kk < 64; kk++) {
            const float4 p = *(const float4*)&Ss[kk * SPAD + tx * 4];
            const float4 v = *(const float4*)&Vs[kk * 64 + ty * 4];
            const float pa[4] = {p.x, p.y, p.z, p.w};
            const float va[4] = {v.x, v.y, v.z, v.w};
#pragma unroll
            for (int i = 0; i < 4; i++)
#pragma unroll
                for (int j = 0; j < 4; j++)
                    acc[i][j] += pa[i] * va[j];
        }
    }

    __syncthreads();
#pragma unroll
    for (int ii = 0; ii < 4; ii++) {
        const int r = tx * 4 + ii;
        const float inv = 1.0f / l_s[r];
        const int row = qt * 64 + r;
        const size_t base = ((size_t)b * Tq + row) * Dd + h * 64 + ty * 4;
        __align__(8) __nv_bfloat16 hv[4], lv[4];
#pragma unroll
        for (int j = 0; j < 4; j++) {
            const float v = acc[ii][j] * inv;
            hv[j] = __float2bfloat16(v);
            lv[j] = __float2bfloat16(v - __bfloat162float(hv[j]));
        }
        *(uint2*)&outh[base] = *(uint2*)hv;
        *(uint2*)&outl[base] = *(uint2*)lv;
    }
}

// ======================= launch =============================================
extern "C" void kernel_launch(void* const* d_in, const int* in_sizes, int n_in,
                              void* d_out, int out_size)
{
    const float* feats = (const float*)d_in[0];
    const float* inps  = (const float*)d_in[1];
    const int*   mask  = (const int*)d_in[2];
    const float* W_f  = (const float*)d_in[3];
    const float* b_f  = (const float*)d_in[4];
    const float* W_i  = (const float*)d_in[5];
    const float* b_i  = (const float*)d_in[6];
    const float* Wu_v = (const float*)d_in[7];
    const float* bu_v = (const float*)d_in[8];
    const float* Wu_l = (const float*)d_in[9];
    const float* bu_l = (const float*)d_in[10];
    float* out = (float*)d_out;

    float *pf, *pi;
    cudaGetSymbolAddress((void**)&pf, g_proj_f);
    cudaGetSymbolAddress((void**)&pi, g_proj_i);
    __nv_bfloat16 *fh, *fl, *ih, *il, *wh, *wl;
    __nv_bfloat16 *avh, *avl, *alh, *all_;
    cudaGetSymbolAddress((void**)&fh, g_fh);   cudaGetSymbolAddress((void**)&fl, g_fl);
    cudaGetSymbolAddress((void**)&ih, g_ih);   cudaGetSymbolAddress((void**)&il, g_il);
    cudaGetSymbolAddress((void**)&wh, g_wh);   cudaGetSymbolAddress((void**)&wl, g_wl);
    cudaGetSymbolAddress((void**)&avh, g_avh); cudaGetSymbolAddress((void**)&avl, g_avl);
    cudaGetSymbolAddress((void**)&alh, g_alh); cudaGetSymbolAddress((void**)&all_, g_all);

    const size_t SF = (size_t)Bb * T1c * Dd;  // 6291456
    const size_t SI = (size_t)Bb * T2c * Dd;  // 786432
    const size_t WSZ = (size_t)Dd * Dd;       // 589824
    const int NF = (int)SF, NI = (int)SI;

    cudaFuncSetAttribute(gemm_mma, cudaFuncAttributeMaxDynamicSharedMemorySize, GEMM_SMEM);
    const int fsm = (3 * 64 * SPAD + 64 * 64 + 3 * 64 + (T1c + T2c)) * (int)sizeof(float);
    cudaFuncSetAttribute(flash_kernel, cudaFuncAttributeMaxDynamicSharedMemorySize, fsm);

    // Exactly 3 conversion launches, so launch #4 (= harness-global #6, the one
    // ncu -s 5 -c 1 profiles) is the dominant 2304-block projection gemm_mma.
    conv_split<<<(NF + 255) / 256, 256>>>(feats, fh, fl, NF);                   // 1
    conv_split<<<(NI + 255) / 256, 256>>>(inps, ih, il, NI);                    // 2
    conv_wsplit_all<<<dim3(24, 24, 14), 256>>>(W_f, W_i, Wu_v, Wu_l, wh, wl);   // 3

    // 4: big projection GEMM (profiled)
    gemm_mma<<<dim3(6, 64, 6), 256, GEMM_SMEM>>>(fh, fl, wh, wl, b_f, pf,
                                                 Bb * T1c, T1c, PROJ_SCALE, 0);
    gemm_mma<<<dim3(6, 8, 6), 256, GEMM_SMEM>>>(ih, il, wh + 6 * WSZ, wl + 6 * WSZ,
                                                b_i, pi, Bb * T2c, T2c, PROJ_SCALE, 0);

    // attention (writes bf16 hi/lo directly)
    flash_kernel<<<dim3(8, Hh, Bb), 256, fsm>>>(
        pf + 1 * SF, pf + 3 * SF, pf + 0 * SF, pf + 2 * SF,
        pi + 0 * SI, pi + 1 * SI, mask, avh, avl, T1c);
    flash_kernel<<<dim3(1, Hh, Bb), 256, fsm>>>(
        pi + 2 * SI, pi + 3 * SI, pf + 4 * SF, pf + 5 * SF,
        pi + 4 * SI, pi + 5 * SI, mask, alh, all_, T2c);

    // output projections
    gemm_mma<<<dim3(6, 64, 1), 256, GEMM_SMEM>>>(avh, avl, wh + 12 * WSZ, wl + 12 * WSZ,
                                                 bu_v, out, Bb * T1c, T1c, 1.0f, 1);
    gemm_mma<<<dim3(6, 8, 1), 256, GEMM_SMEM>>>(alh, all_, wh + 13 * WSZ, wl + 13 * WSZ,
                                                bu_l, out + SF, Bb * T2c, T2c, 1.0f, 1);
}

// round 10
// speedup vs baseline: 1.2014x; 1.2014x over previous
#include <cuda_runtime.h>
#include <cuda_fp16.h>
#include <cstdint>
#include <math.h>

#define Hh 12
#define Dd 768
#define T1c 512
#define T2c 64
#define Bb 16
#define SPAD 68

static const float PROJ_SCALE = 0.3535533905932738f; // 64^-0.25
#define NEGBIG (-1e9f)

// ======================= PTX helpers (baseline ISA only) ====================
__device__ __forceinline__ uint32_t smem_to_u32(const void* p) {
    uint32_t a;
    asm("{ .reg .u64 t; cvta.to.shared.u64 t, %1; cvt.u32.u64 %0, t; }" : "=r"(a) : "l"(p));
    return a;
}
__device__ __forceinline__ void cp16(uint32_t saddr, const void* g) {
    asm volatile("cp.async.ca.shared.global [%0], [%1], 16;" :: "r"(saddr), "l"(g));
}
__device__ __forceinline__ void ldsm4(uint32_t* r, uint32_t addr) {
    asm volatile("ldmatrix.sync.aligned.m8n8.x4.shared.b16 {%0,%1,%2,%3}, [%4];"
        : "=r"(r[0]), "=r"(r[1]), "=r"(r[2]), "=r"(r[3]) : "r"(addr));
}
__device__ __forceinline__ void mma_f16(float* c, const uint32_t* a, const uint32_t* b) {
    asm volatile(
        "mma.sync.aligned.m16n8k16.row.col.f32.f16.f16.f32 "
        "{%0,%1,%2,%3}, {%4,%5,%6,%7}, {%8,%9}, {%0,%1,%2,%3};"
        : "+f"(c[0]), "+f"(c[1]), "+f"(c[2]), "+f"(c[3])
        : "r"(a[0]), "r"(a[1]), "r"(a[2]), "r"(a[3]), "r"(b[0]), "r"(b[1]));
}

// ======================= scratch (device globals) ===========================
__device__ float g_proj_f[6ull * Bb * T1c * Dd];   // [6][B][H][T1][64]
__device__ float g_proj_i[6ull * Bb * T2c * Dd];   // [6][B][H][T2][64]

__device__ __half g_fh[(size_t)Bb * T1c * Dd], g_fl[(size_t)Bb * T1c * Dd];
__device__ __half g_ih[(size_t)Bb * T2c * Dd], g_il[(size_t)Bb * T2c * Dd];
// 14 weight matrices, single fp16, K-major [z][N][K]: [0..5]=W_f [6..11]=W_i [12]=Wu_v [13]=Wu_l
__device__ __half g_wh[14ull * Dd * Dd];
__device__ __half g_avh[(size_t)Bb * T1c * Dd], g_avl[(size_t)Bb * T1c * Dd];
__device__ __half g_alh[(size_t)Bb * T2c * Dd], g_all[(size_t)Bb * T2c * Dd];

// ======================= conversion kernels =================================
__global__ __launch_bounds__(256) void conv_split(
    const float* __restrict__ x, __half* __restrict__ hi,
    __half* __restrict__ lo, int n)
{
    int i = blockIdx.x * 256 + threadIdx.x;
    if (i < n) {
        float v = x[i];
        __half h = __float2half_rn(v);
        hi[i] = h;
        lo[i] = __float2half_rn(v - __half2float(h));
    }
}

// All 14 weight matrices [K=768][N=768] -> [z][N][K] single fp16 in one launch.
__global__ __launch_bounds__(256) void conv_wsplit_all(
    const float* __restrict__ W_f, const float* __restrict__ W_i,
    const float* __restrict__ Wu_v, const float* __restrict__ Wu_l,
    __half* __restrict__ bh)
{
    __shared__ float t[32][33];
    const int z = blockIdx.z;
    const float* Wz;
    if (z < 6)       Wz = W_f  + (size_t)z * Dd * Dd;
    else if (z < 12) Wz = W_i  + (size_t)(z - 6) * Dd * Dd;
    else if (z == 12) Wz = Wu_v;
    else             Wz = Wu_l;
    const int k0 = blockIdx.y * 32, n0 = blockIdx.x * 32;
    const int tx = threadIdx.x & 31, ty = threadIdx.x >> 5; // 32 x 8
#pragma unroll
    for (int j = 0; j < 32; j += 8)
        t[ty + j][tx] = Wz[(size_t)(k0 + ty + j) * Dd + n0 + tx];
    __syncthreads();
#pragma unroll
    for (int j = 0; j < 32; j += 8) {
        float v = t[tx][ty + j];  // = W[k0+tx][n0+ty+j]
        size_t o = (size_t)z * Dd * Dd + (size_t)(n0 + ty + j) * Dd + k0 + tx;
        bh[o] = __float2half_rn(v);
    }
}

// ======================= mma.sync fp16x2 GEMM ===============================
// C = A[M,768] @ W[768,768] (+bias)(*scale); A as fp16 hi+lo pair, W single fp16.
// Product: (Ah + Al) * Bh  (2 MMAs per fragment pair; weight-rounding err ~2^-12).
// B operand K-major [z][N][K]. Tile 128x128, BK=32, double-buffered cp.async.
// 8 warps: warp tile 32x64 (wm = wid&3, wn = wid>>2), m16n8k16 2x8 per warp.
#define ROWB 80                 // 32 halfs + 8 pad = 80 bytes/row
#define TILE_B (128 * ROWB)     // 10240
#define STAGE_B (3 * TILE_B)    // 30720: [Ah | Al | Bh]
#define GEMM_SMEM (2 * STAGE_B) // 61440

__global__ __launch_bounds__(256, 2) void gemm_mma(
    const __half* __restrict__ Ah, const __half* __restrict__ Al,
    const __half* __restrict__ Bh,
    const float* __restrict__ biasbase, float* __restrict__ Cbase,
    int M, int T, float scale, int mode)
{
    extern __shared__ __align__(16) char smem[];
    const uint32_t sb = smem_to_u32(smem);
    const int tid = threadIdx.x, lane = tid & 31, wid = tid >> 5;
    const int wm = wid & 3, wn = wid >> 2;          // warp tile 32m x 64n
    const int z = blockIdx.z;
    const int m0 = blockIdx.y * 128, n0 = blockIdx.x * 128;

    const __half* srcs[3];
    srcs[0] = Ah; srcs[1] = Al;
    srcs[2] = Bh + (size_t)z * Dd * Dd;

    float acc[2][8][4];
#pragma unroll
    for (int a = 0; a < 2; a++)
#pragma unroll
        for (int b = 0; b < 8; b++)
#pragma unroll
            for (int c = 0; c < 4; c++) acc[a][b][c] = 0.0f;

#define LOAD_STAGE(kc, s) do {                                                \
    _Pragma("unroll")                                                         \
    for (int t_ = 0; t_ < 3; t_++) {                                          \
        const __half* src_ = srcs[t_];                                        \
        const int rowbase_ = (t_ < 2) ? m0 : n0;                              \
        _Pragma("unroll")                                                     \
        for (int u_ = 0; u_ < 2; u_++) {                                      \
            const int idx_ = tid * 2 + u_;                                    \
            const int row_ = idx_ >> 2, cc_ = idx_ & 3;                       \
            cp16(sb + (s) * STAGE_B + t_ * TILE_B + row_ * ROWB + cc_ * 16,   \
                 src_ + (size_t)(rowbase_ + row_) * Dd + (kc) * 32 + cc_ * 8);\
        }                                                                     \
    }                                                                         \
    asm volatile("cp.async.commit_group;" ::: "memory");                      \
} while (0)

    LOAD_STAGE(0, 0);

    for (int i = 0; i < 24; i++) {
        const int s = i & 1;
        if (i + 1 < 24) {
            LOAD_STAGE(i + 1, s ^ 1);
            asm volatile("cp.async.wait_group 1;" ::: "memory");
        } else {
            asm volatile("cp.async.wait_group 0;" ::: "memory");
        }
        __syncthreads();

        const uint32_t st = sb + s * STAGE_B;
#pragma unroll
        for (int ks = 0; ks < 2; ks++) {
            const int kb = ks * 32;   // byte offset along K within the row
            // B fragments: 8 n8k16 frags from 4 ldsm (non-trans, [n][k] layout)
            uint32_t b[8][2];
#pragma unroll
            for (int p = 0; p < 4; p++) {
                uint32_t r[4];
                uint32_t ab = st + 2 * TILE_B +
                              (wn * 64 + p * 16 + (lane & 15)) * ROWB +
                              ((lane >> 4) * 16) + kb;
                ldsm4(r, ab);
                b[p * 2][0] = r[0]; b[p * 2 + 1][0] = r[1];
                b[p * 2][1] = r[2]; b[p * 2 + 1][1] = r[3];
            }
            // A fragments hi + lo: 2 m16k16 frags each
            uint32_t ah[2][4], al[2][4];
#pragma unroll
            for (int mt = 0; mt < 2; mt++) {
                const uint32_t ar = (wm * 32 + mt * 16 + (lane & 15)) * ROWB +
                                    ((lane >> 4) * 16) + kb;
                ldsm4(ah[mt], st + ar);
                ldsm4(al[mt], st + TILE_B + ar);
            }
#pragma unroll
            for (int mt = 0; mt < 2; mt++)
#pragma unroll
                for (int nt = 0; nt < 8; nt++) {
                    mma_f16(acc[mt][nt], ah[mt], b[nt]);
                    mma_f16(acc[mt][nt], al[mt], b[nt]);
                }
        }
        __syncthreads();
    }

    // epilogue: fragment -> global (float2 stores)
    const float* bias = biasbase + (size_t)z * Dd;
    float* C = Cbase + (size_t)z * M * Dd;
#pragma unroll
    for (int mt = 0; mt < 2; mt++)
#pragma unroll
        for (int nt = 0; nt < 8; nt++) {
            const int n = n0 + wn * 64 + nt * 8 + (lane & 3) * 2;
            const float2 bv = *(const float2*)&bias[n];
#pragma unroll
            for (int hf = 0; hf < 2; hf++) {
                const int m = m0 + wm * 32 + mt * 16 + (lane >> 2) + hf * 8;
                float2 v;
                v.x = scale * (acc[mt][nt][hf * 2 + 0] + bv.x);
                v.y = scale * (acc[mt][nt][hf * 2 + 1] + bv.y);
                if (mode == 0) {
                    const int b_ = m / T, t_ = m - b_ * T;
                    const int h = n >> 6, e = n & 63;
                    *(float2*)&C[((((size_t)(b_ * Hh + h)) * T + t_) << 6) + e] = v;
                } else {
                    *(float2*)&C[(size_t)m * Dd + n] = v;
                }
            }
        }
}

// ======================= flash attention (fp16 hi/lo epilogue) ==============
__global__ __launch_bounds__(256) void flash_kernel(
    const float* __restrict__ Q1,
    const float* __restrict__ Q2,
    const float* __restrict__ K1,
    const float* __restrict__ V1,
    const float* __restrict__ K2,
    const float* __restrict__ V2,
    const int* __restrict__ mask,
    __half* __restrict__ outh,
    __half* __restrict__ outl,
    int Tq)
{
    extern __shared__ __align__(16) float sm[];
    float* Qs   = sm;
    float* Ks   = Qs + 64 * SPAD;
    float* Vs   = Ks + 64 * SPAD;
    float* Ss   = Vs + 64 * 64;
    float* m_s  = Ss + 64 * SPAD;
    float* l_s  = m_s + 64;
    float* corr = l_s + 64;
    float* mflag = corr + 64;

    const int tid = threadIdx.x;
    const int tx = tid & 15;
    const int ty = tid >> 4;
    const int b = blockIdx.z, h = blockIdx.y, qt = blockIdx.x;

    const float* Q1p = Q1 + (((size_t)(b * Hh + h) * Tq) + qt * 64) * 64;
    const float* Q2p = Q2 + (((size_t)(b * Hh + h) * Tq) + qt * 64) * 64;
    const float* K1p = K1 + ((size_t)(b * Hh + h) * T1c) * 64;
    const float* V1p = V1 + ((size_t)(b * Hh + h) * T1c) * 64;
    const float* K2p = K2 + ((size_t)(b * Hh + h) * T2c) * 64;
    const float* V2p = V2 + ((size_t)(b * Hh + h) * T2c) * 64;

    for (int i = tid; i < 64 * 64; i += 256) {
        const int r = i >> 6, e = i & 63;
        Qs[e * SPAD + r] = Q1p[i];
    }
    for (int j = tid; j < T1c + T2c; j += 256)
        mflag[j] = (mask[b * (T1c + T2c) + j] != 0) ? 1.0f : 0.0f;
    if (tid < 64) { m_s[tid] = -1e30f; l_s[tid] = 0.0f; }

    float acc[4][4];
#pragma unroll
    for (int i = 0; i < 4; i++)
#pragma unroll
        for (int j = 0; j < 4; j++) acc[i][j] = 0.0f;

    for (int kt = 0; kt < 9; kt++) {
        const float* Kt;
        const float* Vt;
        int koff;
        if (kt < 8) { Kt = K1p + kt * 64 * 64; Vt = V1p + kt * 64 * 64; koff = kt * 64; }
        else        { Kt = K2p;               Vt = V2p;               koff = T1c; }

        __syncthreads();
        if (kt == 8) {
            for (int i = tid; i < 64 * 64; i += 256) {
                const int r = i >> 6, e = i & 63;
                Qs[e * SPAD + r] = Q2p[i];
            }
        }
        for (int i = tid; i < 64 * 64; i += 256) {
            const int j = i >> 6, e = i & 63;
            Ks[e * SPAD + j] = Kt[i];
        }
        for (int i = tid * 4; i < 64 * 64; i += 256 * 4)
            *(float4*)&Vs[i] = *(const float4*)&Vt[i];
        __syncthreads();

        float s[4][4];
#pragma unroll
        for (int i = 0; i < 4; i++)
#pragma unroll
            for (int j = 0; j < 4; j++) s[i][j] = 0.0f;
#pragma unroll 8
        for (int e = 0; e < 64; e++) {
            const float4 q  = *(const float4*)&Qs[e * SPAD + tx * 4];
            const float4 kv = *(const float4*)&Ks[e * SPAD + ty * 4];
            const float qa[4] = {q.x, q.y, q.z, q.w};
            const float ka[4] = {kv.x, kv.y, kv.z, kv.w};
#pragma unroll
            for (int i = 0; i < 4; i++)
#pragma unroll
                for (int j = 0; j < 4; j++)
                    s[i][j] += qa[i] * ka[j];
        }
#pragma unroll
        for (int jj = 0; jj < 4; jj++) {
            const float mf = mflag[koff + ty * 4 + jj];
            float4 v;
            v.x = (mf != 0.0f) ? NEGBIG : s[0][jj];
            v.y = (mf != 0.0f) ? NEGBIG : s[1][jj];
            v.z = (mf != 0.0f) ? NEGBIG : s[2][jj];
            v.w = (mf != 0.0f) ? NEGBIG : s[3][jj];
            *(float4*)&Ss[(ty * 4 + jj) * SPAD + tx * 4] = v;
        }
        __syncthreads();

        if (tid < 64) {
            const float mold = m_s[tid];
            float mx = mold;
            for (int j = 0; j < 64; j++) mx = fmaxf(mx, Ss[j * SPAD + tid]);
            const float c = __expf(mold - mx);
            float sum = 0.0f;
            for (int j = 0; j < 64; j++) {
                const float p = __expf(Ss[j * SPAD + tid] - mx);
                Ss[j * SPAD + tid] = p;
                sum += p;
            }
            l_s[tid] = l_s[tid] * c + sum;
            m_s[tid] = mx;
            corr[tid] = c;
        }
        __syncthreads();

        const float c0 = corr[tx * 4 + 0];
        const float c1 = corr[tx * 4 + 1];
        const float c2 = corr[tx * 4 + 2];
        const float c3 = corr[tx * 4 + 3];
#pragma unroll
        for (int j = 0; j < 4; j++) {
            acc[0][j] *= c0; acc[1][j] *= c1; acc[2][j] *= c2; acc[3][j] *= c3;
        }
#pragma unroll 8
        for (int kk = 0; kk < 64; kk++) {
            const float4 p = *(const float4*)&Ss[kk * SPAD + tx * 4];
            const float4 v = *(const float4*)&Vs[kk * 64 + ty * 4];
            const float pa[4] = {p.x, p.y, p.z, p.w};
            const float va[4] = {v.x, v.y, v.z, v.w};
#pragma unroll
            for (int i = 0; i < 4; i++)
#pragma unroll
                for (int j = 0; j < 4; j++)
                    acc[i][j] += pa[i] * va[j];
        }
    }

    __syncthreads();
#pragma unroll
    for (int ii = 0; ii < 4; ii++) {
        const int r = tx * 4 + ii;
        const float inv = 1.0f / l_s[r];
        const int row = qt * 64 + r;
        const size_t base = ((size_t)b * Tq + row) * Dd + h * 64 + ty * 4;
        __align__(8) __half hv[4], lv[4];
#pragma unroll
        for (int j = 0; j < 4; j++) {
            const float v = acc[ii][j] * inv;
            hv[j] = __float2half_rn(v);
            lv[j] = __float2half_rn(v - __half2float(hv[j]));
        }
        *(uint2*)&outh[base] = *(uint2*)hv;
        *(uint2*)&outl[base] = *(uint2*)lv;
    }
}

// ======================= launch =============================================
extern "C" void kernel_launch(void* const* d_in, const int* in_sizes, int n_in,
                              void* d_out, int out_size)
{
    const float* feats = (const float*)d_in[0];
    const float* inps  = (const float*)d_in[1];
    const int*   mask  = (const int*)d_in[2];
    const float* W_f  = (const float*)d_in[3];
    const float* b_f  = (const float*)d_in[4];
    const float* W_i  = (const float*)d_in[5];
    const float* b_i  = (const float*)d_in[6];
    const float* Wu_v = (const float*)d_in[7];
    const float* bu_v = (const float*)d_in[8];
    const float* Wu_l = (const float*)d_in[9];
    const float* bu_l = (const float*)d_in[10];
    float* out = (float*)d_out;

    float *pf, *pi;
    cudaGetSymbolAddress((void**)&pf, g_proj_f);
    cudaGetSymbolAddress((void**)&pi, g_proj_i);
    __half *fh, *fl, *ih, *il, *wh;
    __half *avh, *avl, *alh, *all_;
    cudaGetSymbolAddress((void**)&fh, g_fh);   cudaGetSymbolAddress((void**)&fl, g_fl);
    cudaGetSymbolAddress((void**)&ih, g_ih);   cudaGetSymbolAddress((void**)&il, g_il);
    cudaGetSymbolAddress((void**)&wh, g_wh);
    cudaGetSymbolAddress((void**)&avh, g_avh); cudaGetSymbolAddress((void**)&avl, g_avl);
    cudaGetSymbolAddress((void**)&alh, g_alh); cudaGetSymbolAddress((void**)&all_, g_all);

    const size_t SF = (size_t)Bb * T1c * Dd;  // 6291456
    const size_t SI = (size_t)Bb * T2c * Dd;  // 786432
    const size_t WSZ = (size_t)Dd * Dd;       // 589824
    const int NF = (int)SF, NI = (int)SI;

    cudaFuncSetAttribute(gemm_mma, cudaFuncAttributeMaxDynamicSharedMemorySize, GEMM_SMEM);
    const int fsm = (3 * 64 * SPAD + 64 * 64 + 3 * 64 + (T1c + T2c)) * (int)sizeof(float);
    cudaFuncSetAttribute(flash_kernel, cudaFuncAttributeMaxDynamicSharedMemorySize, fsm);

    // 3 conversion launches; launch #4 = profiled big projection gemm_mma.
    conv_split<<<(NF + 255) / 256, 256>>>(feats, fh, fl, NF);                   // 1
    conv_split<<<(NI + 255) / 256, 256>>>(inps, ih, il, NI);                    // 2
    conv_wsplit_all<<<dim3(24, 24, 14), 256>>>(W_f, W_i, Wu_v, Wu_l, wh);       // 3

    // 4: big projection GEMM (profiled)
    gemm_mma<<<dim3(6, 64, 6), 256, GEMM_SMEM>>>(fh, fl, wh, b_f, pf,
                                                 Bb * T1c, T1c, PROJ_SCALE, 0);
    gemm_mma<<<dim3(6, 8, 6), 256, GEMM_SMEM>>>(ih, il, wh + 6 * WSZ, b_i, pi,
                                                Bb * T2c, T2c, PROJ_SCALE, 0);

    // attention (writes fp16 hi/lo directly)
    flash_kernel<<<dim3(8, Hh, Bb), 256, fsm>>>(
        pf + 1 * SF, pf + 3 * SF, pf + 0 * SF, pf + 2 * SF,
        pi + 0 * SI, pi + 1 * SI, mask, avh, avl, T1c);
    flash_kernel<<<dim3(1, Hh, Bb), 256, fsm>>>(
        pi + 2 * SI, pi + 3 * SI, pf + 4 * SF, pf + 5 * SF,
        pi + 4 * SI, pi + 5 * SI, mask, alh, all_, T2c);

    // output projections
    gemm_mma<<<dim3(6, 64, 1), 256, GEMM_SMEM>>>(avh, avl, wh + 12 * WSZ,
                                                 bu_v, out, Bb * T1c, T1c, 1.0f, 1);
    gemm_mma<<<dim3(6, 8, 1), 256, GEMM_SMEM>>>(alh, all_, wh + 13 * WSZ,
                                                bu_l, out + SF, Bb * T2c, T2c, 1.0f, 1);
}

// round 11
// speedup vs baseline: 1.4681x; 1.2220x over previous
#include <cuda_runtime.h>
#include <cuda_fp16.h>
#include <cstdint>
#include <math.h>

#define Hh 12
#define Dd 768
#define T1c 512
#define T2c 64
#define Bb 16
#define SPAD 68

static const float PROJ_SCALE = 0.3535533905932738f; // 64^-0.25
#define NEGBIG (-1e9f)

// ======================= PTX helpers (baseline ISA only) ====================
__device__ __forceinline__ uint32_t smem_to_u32(const void* p) {
    uint32_t a;
    asm("{ .reg .u64 t; cvta.to.shared.u64 t, %1; cvt.u32.u64 %0, t; }" : "=r"(a) : "l"(p));
    return a;
}
__device__ __forceinline__ void cp16(uint32_t saddr, const void* g) {
    asm volatile("cp.async.ca.shared.global [%0], [%1], 16;" :: "r"(saddr), "l"(g));
}
__device__ __forceinline__ void ldsm4(uint32_t* r, uint32_t addr) {
    asm volatile("ldmatrix.sync.aligned.m8n8.x4.shared.b16 {%0,%1,%2,%3}, [%4];"
        : "=r"(r[0]), "=r"(r[1]), "=r"(r[2]), "=r"(r[3]) : "r"(addr));
}
__device__ __forceinline__ void mma_f16(float* c, const uint32_t* a, const uint32_t* b) {
    asm volatile(
        "mma.sync.aligned.m16n8k16.row.col.f32.f16.f16.f32 "
        "{%0,%1,%2,%3}, {%4,%5,%6,%7}, {%8,%9}, {%0,%1,%2,%3};"
        : "+f"(c[0]), "+f"(c[1]), "+f"(c[2]), "+f"(c[3])
        : "r"(a[0]), "r"(a[1]), "r"(a[2]), "r"(a[3]), "r"(b[0]), "r"(b[1]));
}

// ======================= scratch (device globals) ===========================
__device__ float g_proj_f[6ull * Bb * T1c * Dd];   // [6][B][H][T1][64]
__device__ float g_proj_i[6ull * Bb * T2c * Dd];   // [6][B][H][T2][64]

__device__ __half g_fa[(size_t)Bb * T1c * Dd];
__device__ __half g_ia[(size_t)Bb * T2c * Dd];
// 14 weight matrices, fp16, K-major [z][N][K]: [0..5]=W_f [6..11]=W_i [12]=Wu_v [13]=Wu_l
__device__ __half g_wh[14ull * Dd * Dd];
__device__ __half g_av[(size_t)Bb * T1c * Dd];
__device__ __half g_al[(size_t)Bb * T2c * Dd];

// ======================= conversion kernels =================================
__global__ __launch_bounds__(256) void conv_f16(
    const float* __restrict__ x, __half* __restrict__ o, int n)
{
    int i = blockIdx.x * 256 + threadIdx.x;
    if (i < n) o[i] = __float2half_rn(x[i]);
}

// All 14 weight matrices [K=768][N=768] -> [z][N][K] fp16 in one launch.
__global__ __launch_bounds__(256) void conv_wsplit_all(
    const float* __restrict__ W_f, const float* __restrict__ W_i,
    const float* __restrict__ Wu_v, const float* __restrict__ Wu_l,
    __half* __restrict__ bh)
{
    __shared__ float t[32][33];
    const int z = blockIdx.z;
    const float* Wz;
    if (z < 6)       Wz = W_f  + (size_t)z * Dd * Dd;
    else if (z < 12) Wz = W_i  + (size_t)(z - 6) * Dd * Dd;
    else if (z == 12) Wz = Wu_v;
    else             Wz = Wu_l;
    const int k0 = blockIdx.y * 32, n0 = blockIdx.x * 32;
    const int tx = threadIdx.x & 31, ty = threadIdx.x >> 5; // 32 x 8
#pragma unroll
    for (int j = 0; j < 32; j += 8)
        t[ty + j][tx] = Wz[(size_t)(k0 + ty + j) * Dd + n0 + tx];
    __syncthreads();
#pragma unroll
    for (int j = 0; j < 32; j += 8) {
        float v = t[tx][ty + j];  // = W[k0+tx][n0+ty+j]
        size_t o = (size_t)z * Dd * Dd + (size_t)(n0 + ty + j) * Dd + k0 + tx;
        bh[o] = __float2half_rn(v);
    }
}

// ======================= mma.sync fp16 GEMM =================================
// C = A[M,768] @ W[768,768] (+bias)(*scale); A and W single fp16 (err ~2^-12 ea).
// B operand K-major [z][N][K]. Tile 128x128, BK=32, double-buffered cp.async.
// 8 warps: warp tile 32x64 (wm = wid&3, wn = wid>>2), m16n8k16 2x8 per warp, 1 MMA/pair.
#define ROWB 80                 // 32 halfs + 8 pad = 80 bytes/row
#define TILE_B (128 * ROWB)     // 10240
#define STAGE_B (2 * TILE_B)    // 20480: [A | B]
#define GEMM_SMEM (2 * STAGE_B) // 40960

__global__ __launch_bounds__(256, 2) void gemm_mma(
    const __half* __restrict__ Ah,
    const __half* __restrict__ Bh,
    const float* __restrict__ biasbase, float* __restrict__ Cbase,
    int M, int T, float scale, int mode)
{
    extern __shared__ __align__(16) char smem[];
    const uint32_t sb = smem_to_u32(smem);
    const int tid = threadIdx.x, lane = tid & 31, wid = tid >> 5;
    const int wm = wid & 3, wn = wid >> 2;          // warp tile 32m x 64n
    const int z = blockIdx.z;
    const int m0 = blockIdx.y * 128, n0 = blockIdx.x * 128;

    const __half* srcs[2];
    srcs[0] = Ah;
    srcs[1] = Bh + (size_t)z * Dd * Dd;

    float acc[2][8][4];
#pragma unroll
    for (int a = 0; a < 2; a++)
#pragma unroll
        for (int b = 0; b < 8; b++)
#pragma unroll
            for (int c = 0; c < 4; c++) acc[a][b][c] = 0.0f;

#define LOAD_STAGE(kc, s) do {                                                \
    _Pragma("unroll")                                                         \
    for (int t_ = 0; t_ < 2; t_++) {                                          \
        const __half* src_ = srcs[t_];                                        \
        const int rowbase_ = (t_ < 1) ? m0 : n0;                              \
        _Pragma("unroll")                                                     \
        for (int u_ = 0; u_ < 2; u_++) {                                      \
            const int idx_ = tid * 2 + u_;                                    \
            const int row_ = idx_ >> 2, cc_ = idx_ & 3;                       \
            cp16(sb + (s) * STAGE_B + t_ * TILE_B + row_ * ROWB + cc_ * 16,   \
                 src_ + (size_t)(rowbase_ + row_) * Dd + (kc) * 32 + cc_ * 8);\
        }                                                                     \
    }                                                                         \
    asm volatile("cp.async.commit_group;" ::: "memory");                      \
} while (0)

    LOAD_STAGE(0, 0);

    for (int i = 0; i < 24; i++) {
        const int s = i & 1;
        if (i + 1 < 24) {
            LOAD_STAGE(i + 1, s ^ 1);
            asm volatile("cp.async.wait_group 1;" ::: "memory");
        } else {
            asm volatile("cp.async.wait_group 0;" ::: "memory");
        }
        __syncthreads();

        const uint32_t st = sb + s * STAGE_B;
#pragma unroll
        for (int ks = 0; ks < 2; ks++) {
            const int kb = ks * 32;   // byte offset along K within the row
            // B fragments: 8 n8k16 frags from 4 ldsm (non-trans, [n][k] layout)
            uint32_t b[8][2];
#pragma unroll
            for (int p = 0; p < 4; p++) {
                uint32_t r[4];
                uint32_t ab = st + TILE_B +
                              (wn * 64 + p * 16 + (lane & 15)) * ROWB +
                              ((lane >> 4) * 16) + kb;
                ldsm4(r, ab);
                b[p * 2][0] = r[0]; b[p * 2 + 1][0] = r[1];
                b[p * 2][1] = r[2]; b[p * 2 + 1][1] = r[3];
            }
            // A fragments: 2 m16k16 frags
            uint32_t a[2][4];
#pragma unroll
            for (int mt = 0; mt < 2; mt++) {
                const uint32_t ar = (wm * 32 + mt * 16 + (lane & 15)) * ROWB +
                                    ((lane >> 4) * 16) + kb;
                ldsm4(a[mt], st + ar);
            }
#pragma unroll
            for (int mt = 0; mt < 2; mt++)
#pragma unroll
                for (int nt = 0; nt < 8; nt++)
                    mma_f16(acc[mt][nt], a[mt], b[nt]);
        }
        __syncthreads();
    }

    // epilogue: fragment -> global (float2 stores)
    const float* bias = biasbase + (size_t)z * Dd;
    float* C = Cbase + (size_t)z * M * Dd;
#pragma unroll
    for (int mt = 0; mt < 2; mt++)
#pragma unroll
        for (int nt = 0; nt < 8; nt++) {
            const int n = n0 + wn * 64 + nt * 8 + (lane & 3) * 2;
            const float2 bv = *(const float2*)&bias[n];
#pragma unroll
            for (int hf = 0; hf < 2; hf++) {
                const int m = m0 + wm * 32 + mt * 16 + (lane >> 2) + hf * 8;
                float2 v;
                v.x = scale * (acc[mt][nt][hf * 2 + 0] + bv.x);
                v.y = scale * (acc[mt][nt][hf * 2 + 1] + bv.y);
                if (mode == 0) {
                    const int b_ = m / T, t_ = m - b_ * T;
                    const int h = n >> 6, e = n & 63;
                    *(float2*)&C[((((size_t)(b_ * Hh + h)) * T + t_) << 6) + e] = v;
                } else {
                    *(float2*)&C[(size_t)m * Dd + n] = v;
                }
            }
        }
}

// ======================= flash attention (fp16 epilogue) ====================
__global__ __launch_bounds__(256) void flash_kernel(
    const float* __restrict__ Q1,
    const float* __restrict__ Q2,
    const float* __restrict__ K1,
    const float* __restrict__ V1,
    const float* __restrict__ K2,
    const float* __restrict__ V2,
    const int* __restrict__ mask,
    __half* __restrict__ outh,
    int Tq)
{
    extern __shared__ __align__(16) float sm[];
    float* Qs   = sm;
    float* Ks   = Qs + 64 * SPAD;
    float* Vs   = Ks + 64 * SPAD;
    float* Ss   = Vs + 64 * 64;
    float* m_s  = Ss + 64 * SPAD;
    float* l_s  = m_s + 64;
    float* corr = l_s + 64;
    float* mflag = corr + 64;

    const int tid = threadIdx.x;
    const int tx = tid & 15;
    const int ty = tid >> 4;
    const int b = blockIdx.z, h = blockIdx.y, qt = blockIdx.x;

    const float* Q1p = Q1 + (((size_t)(b * Hh + h) * Tq) + qt * 64) * 64;
    const float* Q2p = Q2 + (((size_t)(b * Hh + h) * Tq) + qt * 64) * 64;
    const float* K1p = K1 + ((size_t)(b * Hh + h) * T1c) * 64;
    const float* V1p = V1 + ((size_t)(b * Hh + h) * T1c) * 64;
    const float* K2p = K2 + ((size_t)(b * Hh + h) * T2c) * 64;
    const float* V2p = V2 + ((size_t)(b * Hh + h) * T2c) * 64;

    for (int i = tid; i < 64 * 64; i += 256) {
        const int r = i >> 6, e = i & 63;
        Qs[e * SPAD + r] = Q1p[i];
    }
    for (int j = tid; j < T1c + T2c; j += 256)
        mflag[j] = (mask[b * (T1c + T2c) + j] != 0) ? 1.0f : 0.0f;
    if (tid < 64) { m_s[tid] = -1e30f; l_s[tid] = 0.0f; }

    float acc[4][4];
#pragma unroll
    for (int i = 0; i < 4; i++)
#pragma unroll
        for (int j = 0; j < 4; j++) acc[i][j] = 0.0f;

    for (int kt = 0; kt < 9; kt++) {
        const float* Kt;
        const float* Vt;
        int koff;
        if (kt < 8) { Kt = K1p + kt * 64 * 64; Vt = V1p + kt * 64 * 64; koff = kt * 64; }
        else        { Kt = K2p;               Vt = V2p;               koff = T1c; }

        __syncthreads();
        if (kt == 8) {
            for (int i = tid; i < 64 * 64; i += 256) {
                const int r = i >> 6, e = i & 63;
                Qs[e * SPAD + r] = Q2p[i];
            }
        }
        for (int i = tid; i < 64 * 64; i += 256) {
            const int j = i >> 6, e = i & 63;
            Ks[e * SPAD + j] = Kt[i];
        }
        for (int i = tid * 4; i < 64 * 64; i += 256 * 4)
            *(float4*)&Vs[i] = *(const float4*)&Vt[i];
        __syncthreads();

        float s[4][4];
#pragma unroll
        for (int i = 0; i < 4; i++)
#pragma unroll
            for (int j = 0; j < 4; j++) s[i][j] = 0.0f;
#pragma unroll 8
        for (int e = 0; e < 64; e++) {
            const float4 q  = *(const float4*)&Qs[e * SPAD + tx * 4];
            const float4 kv = *(const float4*)&Ks[e * SPAD + ty * 4];
            const float qa[4] = {q.x, q.y, q.z, q.w};
            const float ka[4] = {kv.x, kv.y, kv.z, kv.w};
#pragma unroll
            for (int i = 0; i < 4; i++)
#pragma unroll
                for (int j = 0; j < 4; j++)
                    s[i][j] += qa[i] * ka[j];
        }
#pragma unroll
        for (int jj = 0; jj < 4; jj++) {
            const float mf = mflag[koff + ty * 4 + jj];
            float4 v;
            v.x = (mf != 0.0f) ? NEGBIG : s[0][jj];
            v.y = (mf != 0.0f) ? NEGBIG : s[1][jj];
            v.z = (mf != 0.0f) ? NEGBIG : s[2][jj];
            v.w = (mf != 0.0f) ? NEGBIG : s[3][jj];
            *(float4*)&Ss[(ty * 4 + jj) * SPAD + tx * 4] = v;
        }
        __syncthreads();

        if (tid < 64) {
            const float mold = m_s[tid];
            float mx = mold;
            for (int j = 0; j < 64; j++) mx = fmaxf(mx, Ss[j * SPAD + tid]);
            const float c = __expf(mold - mx);
            float sum = 0.0f;
            for (int j = 0; j < 64; j++) {
                const float p = __expf(Ss[j * SPAD + tid] - mx);
                Ss[j * SPAD + tid] = p;
                sum += p;
            }
            l_s[tid] = l_s[tid] * c + sum;
            m_s[tid] = mx;
            corr[tid] = c;
        }
        __syncthreads();

        const float c0 = corr[tx * 4 + 0];
        const float c1 = corr[tx * 4 + 1];
        const float c2 = corr[tx * 4 + 2];
        const float c3 = corr[tx * 4 + 3];
#pragma unroll
        for (int j = 0; j < 4; j++) {
            acc[0][j] *= c0; acc[1][j] *= c1; acc[2][j] *= c2; acc[3][j] *= c3;
        }
#pragma unroll 8
        for (int kk = 0; kk < 64; kk++) {
            const float4 p = *(const float4*)&Ss[kk * SPAD + tx * 4];
            const float4 v = *(const float4*)&Vs[kk * 64 + ty * 4];
            const float pa[4] = {p.x, p.y, p.z, p.w};
            const float va[4] = {v.x, v.y, v.z, v.w};
#pragma unroll
            for (int i = 0; i < 4; i++)
#pragma unroll
                for (int j = 0; j < 4; j++)
                    acc[i][j] += pa[i] * va[j];
        }
    }

    __syncthreads();
#pragma unroll
    for (int ii = 0; ii < 4; ii++) {
        const int r = tx * 4 + ii;
        const float inv = 1.0f / l_s[r];
        const int row = qt * 64 + r;
        const size_t base = ((size_t)b * Tq + row) * Dd + h * 64 + ty * 4;
        __align__(8) __half hv[4];
#pragma unroll
        for (int j = 0; j < 4; j++)
            hv[j] = __float2half_rn(acc[ii][j] * inv);
        *(uint2*)&outh[base] = *(uint2*)hv;
    }
}

// ======================= launch =============================================
extern "C" void kernel_launch(void* const* d_in, const int* in_sizes, int n_in,
                              void* d_out, int out_size)
{
    const float* feats = (const float*)d_in[0];
    const float* inps  = (const float*)d_in[1];
    const int*   mask  = (const int*)d_in[2];
    const float* W_f  = (const float*)d_in[3];
    const float* b_f  = (const float*)d_in[4];
    const float* W_i  = (const float*)d_in[5];
    const float* b_i  = (const float*)d_in[6];
    const float* Wu_v = (const float*)d_in[7];
    const float* bu_v = (const float*)d_in[8];
    const float* Wu_l = (const float*)d_in[9];
    const float* bu_l = (const float*)d_in[10];
    float* out = (float*)d_out;

    float *pf, *pi;
    cudaGetSymbolAddress((void**)&pf, g_proj_f);
    cudaGetSymbolAddress((void**)&pi, g_proj_i);
    __half *fa, *ia, *wh, *av, *al;
    cudaGetSymbolAddress((void**)&fa, g_fa);
    cudaGetSymbolAddress((void**)&ia, g_ia);
    cudaGetSymbolAddress((void**)&wh, g_wh);
    cudaGetSymbolAddress((void**)&av, g_av);
    cudaGetSymbolAddress((void**)&al, g_al);

    const size_t SF = (size_t)Bb * T1c * Dd;  // 6291456
    const size_t SI = (size_t)Bb * T2c * Dd;  // 786432
    const size_t WSZ = (size_t)Dd * Dd;       // 589824
    const int NF = (int)SF, NI = (int)SI;

    cudaFuncSetAttribute(gemm_mma, cudaFuncAttributeMaxDynamicSharedMemorySize, GEMM_SMEM);
    const int fsm = (3 * 64 * SPAD + 64 * 64 + 3 * 64 + (T1c + T2c)) * (int)sizeof(float);
    cudaFuncSetAttribute(flash_kernel, cudaFuncAttributeMaxDynamicSharedMemorySize, fsm);

    // 3 conversion launches; launch #4 = profiled big projection gemm_mma.
    conv_f16<<<(NF + 255) / 256, 256>>>(feats, fa, NF);                         // 1
    conv_f16<<<(NI + 255) / 256, 256>>>(inps, ia, NI);                          // 2
    conv_wsplit_all<<<dim3(24, 24, 14), 256>>>(W_f, W_i, Wu_v, Wu_l, wh);       // 3

    // 4: big projection GEMM (profiled)
    gemm_mma<<<dim3(6, 64, 6), 256, GEMM_SMEM>>>(fa, wh, b_f, pf,
                                                 Bb * T1c, T1c, PROJ_SCALE, 0);
    gemm_mma<<<dim3(6, 8, 6), 256, GEMM_SMEM>>>(ia, wh + 6 * WSZ, b_i, pi,
                                                Bb * T2c, T2c, PROJ_SCALE, 0);

    // attention (writes fp16 directly)
    flash_kernel<<<dim3(8, Hh, Bb), 256, fsm>>>(
        pf + 1 * SF, pf + 3 * SF, pf + 0 * SF, pf + 2 * SF,
        pi + 0 * SI, pi + 1 * SI, mask, av, T1c);
    flash_kernel<<<dim3(1, Hh, Bb), 256, fsm>>>(
        pi + 2 * SI, pi + 3 * SI, pf + 4 * SF, pf + 5 * SF,
        pi + 4 * SI, pi + 5 * SI, mask, al, T2c);

    // output projections
    gemm_mma<<<dim3(6, 64, 1), 256, GEMM_SMEM>>>(av, wh + 12 * WSZ,
                                                 bu_v, out, Bb * T1c, T1c, 1.0f, 1);
    gemm_mma<<<dim3(6, 8, 1), 256, GEMM_SMEM>>>(al, wh + 13 * WSZ,
                                                bu_l, out + SF, Bb * T2c, T2c, 1.0f, 1);
}

// round 12
// speedup vs baseline: 1.4843x; 1.0110x over previous
#include <cuda_runtime.h>
#include <cuda_fp16.h>
#include <cstdint>
#include <math.h>

#define Hh 12
#define Dd 768
#define T1c 512
#define T2c 64
#define Bb 16
#define SPAD 68

static const float PROJ_SCALE = 0.3535533905932738f; // 64^-0.25
#define NEGBIG (-1e9f)

// ======================= PTX helpers (baseline ISA only) ====================
__device__ __forceinline__ uint32_t smem_to_u32(const void* p) {
    uint32_t a;
    asm("{ .reg .u64 t; cvta.to.shared.u64 t, %1; cvt.u32.u64 %0, t; }" : "=r"(a) : "l"(p));
    return a;
}
__device__ __forceinline__ void cp16(uint32_t saddr, const void* g) {
    asm volatile("cp.async.ca.shared.global [%0], [%1], 16;" :: "r"(saddr), "l"(g));
}
__device__ __forceinline__ void ldsm4(uint32_t* r, uint32_t addr) {
    asm volatile("ldmatrix.sync.aligned.m8n8.x4.shared.b16 {%0,%1,%2,%3}, [%4];"
        : "=r"(r[0]), "=r"(r[1]), "=r"(r[2]), "=r"(r[3]) : "r"(addr));
}
__device__ __forceinline__ void mma_f16(float* c, const uint32_t* a, const uint32_t* b) {
    asm volatile(
        "mma.sync.aligned.m16n8k16.row.col.f32.f16.f16.f32 "
        "{%0,%1,%2,%3}, {%4,%5,%6,%7}, {%8,%9}, {%0,%1,%2,%3};"
        : "+f"(c[0]), "+f"(c[1]), "+f"(c[2]), "+f"(c[3])
        : "r"(a[0]), "r"(a[1]), "r"(a[2]), "r"(a[3]), "r"(b[0]), "r"(b[1]));
}

// ======================= scratch (device globals) ===========================
__device__ float g_proj_f[6ull * Bb * T1c * Dd];   // [6][B][H][T1][64]
__device__ float g_proj_i[6ull * Bb * T2c * Dd];   // [6][B][H][T2][64]

__device__ __half g_fa[(size_t)Bb * T1c * Dd];
__device__ __half g_ia[(size_t)Bb * T2c * Dd];
// 14 weight matrices, fp16, K-major [z][N][K]: [0..5]=W_f [6..11]=W_i [12]=Wu_v [13]=Wu_l
__device__ __half g_wh[14ull * Dd * Dd];
__device__ __half g_av[(size_t)Bb * T1c * Dd];
__device__ __half g_al[(size_t)Bb * T2c * Dd];

// ======================= conversion kernels =================================
__global__ __launch_bounds__(256) void conv_f16(
    const float* __restrict__ x, __half* __restrict__ o, int n)
{
    int i = blockIdx.x * 256 + threadIdx.x;
    if (i < n) o[i] = __float2half_rn(x[i]);
}

// All 14 weight matrices [K=768][N=768] -> [z][N][K] fp16 in one launch.
__global__ __launch_bounds__(256) void conv_wsplit_all(
    const float* __restrict__ W_f, const float* __restrict__ W_i,
    const float* __restrict__ Wu_v, const float* __restrict__ Wu_l,
    __half* __restrict__ bh)
{
    __shared__ float t[32][33];
    const int z = blockIdx.z;
    const float* Wz;
    if (z < 6)       Wz = W_f  + (size_t)z * Dd * Dd;
    else if (z < 12) Wz = W_i  + (size_t)(z - 6) * Dd * Dd;
    else if (z == 12) Wz = Wu_v;
    else             Wz = Wu_l;
    const int k0 = blockIdx.y * 32, n0 = blockIdx.x * 32;
    const int tx = threadIdx.x & 31, ty = threadIdx.x >> 5; // 32 x 8
#pragma unroll
    for (int j = 0; j < 32; j += 8)
        t[ty + j][tx] = Wz[(size_t)(k0 + ty + j) * Dd + n0 + tx];
    __syncthreads();
#pragma unroll
    for (int j = 0; j < 32; j += 8) {
        float v = t[tx][ty + j];  // = W[k0+tx][n0+ty+j]
        size_t o = (size_t)z * Dd * Dd + (size_t)(n0 + ty + j) * Dd + k0 + tx;
        bh[o] = __float2half_rn(v);
    }
}

// ======================= mma.sync fp16 GEMM =================================
// C = A[M,768] @ W[768,768] (+bias)(*scale); A and W single fp16.
// B operand K-major [z][N][K]. CTA tile 128x256, BK=32, double-buffered cp.async.
// 8 warps, warp tile 64x64 (wm = wid&1, wn = wid>>1), m16n8k16 4x8 per warp.
// Fat warp tile: 8 ldsm4 per warp-ks for 32 MMAs = 128 B smem per MMA (-33%).
#define ROWB  80                  // 32 halfs + 8 pad = 80 bytes/row
#define TILE_A (128 * ROWB)       // 10240
#define TILE_Bb (256 * ROWB)      // 20480
#define STAGE_B (TILE_A + TILE_Bb) // 30720
#define GEMM_SMEM (2 * STAGE_B)   // 61440

__global__ __launch_bounds__(256, 1) void gemm_mma(
    const __half* __restrict__ Ah,
    const __half* __restrict__ Bh,
    const float* __restrict__ biasbase, float* __restrict__ Cbase,
    int M, int T, float scale, int mode)
{
    extern __shared__ __align__(16) char smem[];
    const uint32_t sb = smem_to_u32(smem);
    const int tid = threadIdx.x, lane = tid & 31, wid = tid >> 5;
    const int wm = wid & 1, wn = wid >> 1;          // warp tile 64m x 64n
    const int z = blockIdx.z;
    const int m0 = blockIdx.y * 128, n0 = blockIdx.x * 256;

    const __half* Asrc = Ah;
    const __half* Bsrc = Bh + (size_t)z * Dd * Dd;

    float acc[4][8][4];
#pragma unroll
    for (int a = 0; a < 4; a++)
#pragma unroll
        for (int b = 0; b < 8; b++)
#pragma unroll
            for (int c = 0; c < 4; c++) acc[a][b][c] = 0.0f;

    // Stage fill: A = 512 cp16 (128 rows x 4 chunks), B = 1024 cp16 (256 rows x 4).
#define LOAD_STAGE(kc, s) do {                                                \
    _Pragma("unroll")                                                         \
    for (int u_ = 0; u_ < 2; u_++) {                                          \
        const int idx_ = tid + u_ * 256;                                      \
        const int row_ = idx_ >> 2, cc_ = idx_ & 3;                           \
        cp16(sb + (s) * STAGE_B + row_ * ROWB + cc_ * 16,                     \
             Asrc + (size_t)(m0 + row_) * Dd + (kc) * 32 + cc_ * 8);          \
    }                                                                         \
    _Pragma("unroll")                                                         \
    for (int u_ = 0; u_ < 4; u_++) {                                          \
        const int idx_ = tid + u_ * 256;                                      \
        const int row_ = idx_ >> 2, cc_ = idx_ & 3;                           \
        cp16(sb + (s) * STAGE_B + TILE_A + row_ * ROWB + cc_ * 16,            \
             Bsrc + (size_t)(n0 + row_) * Dd + (kc) * 32 + cc_ * 8);          \
    }                                                                         \
    asm volatile("cp.async.commit_group;" ::: "memory");                      \
} while (0)

    LOAD_STAGE(0, 0);

    for (int i = 0; i < 24; i++) {
        const int s = i & 1;
        if (i + 1 < 24) {
            LOAD_STAGE(i + 1, s ^ 1);
            asm volatile("cp.async.wait_group 1;" ::: "memory");
        } else {
            asm volatile("cp.async.wait_group 0;" ::: "memory");
        }
        __syncthreads();

        const uint32_t st = sb + s * STAGE_B;
#pragma unroll
        for (int ks = 0; ks < 2; ks++) {
            const int kb = ks * 32;   // byte offset along K within the row
            // B fragments: 8 n8k16 frags from 4 ldsm4 (non-trans, [n][k] layout)
            uint32_t b[8][2];
#pragma unroll
            for (int p = 0; p < 4; p++) {
                uint32_t r[4];
                uint32_t ab = st + TILE_A +
                              (wn * 64 + p * 16 + (lane & 15)) * ROWB +
                              ((lane >> 4) * 16) + kb;
                ldsm4(r, ab);
                b[p * 2][0] = r[0]; b[p * 2 + 1][0] = r[1];
                b[p * 2][1] = r[2]; b[p * 2 + 1][1] = r[3];
            }
            // A fragments: 4 m16k16 frags
            uint32_t a[4][4];
#pragma unroll
            for (int mt = 0; mt < 4; mt++) {
                const uint32_t ar = (wm * 64 + mt * 16 + (lane & 15)) * ROWB +
                                    ((lane >> 4) * 16) + kb;
                ldsm4(a[mt], st + ar);
            }
#pragma unroll
            for (int mt = 0; mt < 4; mt++)
#pragma unroll
                for (int nt = 0; nt < 8; nt++)
                    mma_f16(acc[mt][nt], a[mt], b[nt]);
        }
        __syncthreads();
    }

    // epilogue: fragment -> global (float2 stores)
    const float* bias = biasbase + (size_t)z * Dd;
    float* C = Cbase + (size_t)z * M * Dd;
#pragma unroll
    for (int mt = 0; mt < 4; mt++)
#pragma unroll
        for (int nt = 0; nt < 8; nt++) {
            const int n = n0 + wn * 64 + nt * 8 + (lane & 3) * 2;
            const float2 bv = *(const float2*)&bias[n];
#pragma unroll
            for (int hf = 0; hf < 2; hf++) {
                const int m = m0 + wm * 64 + mt * 16 + (lane >> 2) + hf * 8;
                float2 v;
                v.x = scale * (acc[mt][nt][hf * 2 + 0] + bv.x);
                v.y = scale * (acc[mt][nt][hf * 2 + 1] + bv.y);
                if (mode == 0) {
                    const int b_ = m / T, t_ = m - b_ * T;
                    const int h = n >> 6, e = n & 63;
                    *(float2*)&C[((((size_t)(b_ * Hh + h)) * T + t_) << 6) + e] = v;
                } else {
                    *(float2*)&C[(size_t)m * Dd + n] = v;
                }
            }
        }
}

// ======================= flash attention (fp16 epilogue) ====================
__global__ __launch_bounds__(256) void flash_kernel(
    const float* __restrict__ Q1,
    const float* __restrict__ Q2,
    const float* __restrict__ K1,
    const float* __restrict__ V1,
    const float* __restrict__ K2,
    const float* __restrict__ V2,
    const int* __restrict__ mask,
    __half* __restrict__ outh,
    int Tq)
{
    extern __shared__ __align__(16) float sm[];
    float* Qs   = sm;
    float* Ks   = Qs + 64 * SPAD;
    float* Vs   = Ks + 64 * SPAD;
    float* Ss   = Vs + 64 * 64;
    float* m_s  = Ss + 64 * SPAD;
    float* l_s  = m_s + 64;
    float* corr = l_s + 64;
    float* mflag = corr + 64;

    const int tid = threadIdx.x;
    const int tx = tid & 15;
    const int ty = tid >> 4;
    const int b = blockIdx.z, h = blockIdx.y, qt = blockIdx.x;

    const float* Q1p = Q1 + (((size_t)(b * Hh + h) * Tq) + qt * 64) * 64;
    const float* Q2p = Q2 + (((size_t)(b * Hh + h) * Tq) + qt * 64) * 64;
    const float* K1p = K1 + ((size_t)(b * Hh + h) * T1c) * 64;
    const float* V1p = V1 + ((size_t)(b * Hh + h) * T1c) * 64;
    const float* K2p = K2 + ((size_t)(b * Hh + h) * T2c) * 64;
    const float* V2p = V2 + ((size_t)(b * Hh + h) * T2c) * 64;

    for (int i = tid; i < 64 * 64; i += 256) {
        const int r = i >> 6, e = i & 63;
        Qs[e * SPAD + r] = Q1p[i];
    }
    for (int j = tid; j < T1c + T2c; j += 256)
        mflag[j] = (mask[b * (T1c + T2c) + j] != 0) ? 1.0f : 0.0f;
    if (tid < 64) { m_s[tid] = -1e30f; l_s[tid] = 0.0f; }

    float acc[4][4];
#pragma unroll
    for (int i = 0; i < 4; i++)
#pragma unroll
        for (int j = 0; j < 4; j++) acc[i][j] = 0.0f;

    for (int kt = 0; kt < 9; kt++) {
        const float* Kt;
        const float* Vt;
        int koff;
        if (kt < 8) { Kt = K1p + kt * 64 * 64; Vt = V1p + kt * 64 * 64; koff = kt * 64; }
        else        { Kt = K2p;               Vt = V2p;               koff = T1c; }

        __syncthreads();
        if (kt == 8) {
            for (int i = tid; i < 64 * 64; i += 256) {
                const int r = i >> 6, e = i & 63;
                Qs[e * SPAD + r] = Q2p[i];
            }
        }
        for (int i = tid; i < 64 * 64; i += 256) {
            const int j = i >> 6, e = i & 63;
            Ks[e * SPAD + j] = Kt[i];
        }
        for (int i = tid * 4; i < 64 * 64; i += 256 * 4)
            *(float4*)&Vs[i] = *(const float4*)&Vt[i];
        __syncthreads();

        float s[4][4];
#pragma unroll
        for (int i = 0; i < 4; i++)
#pragma unroll
            for (int j = 0; j < 4; j++) s[i][j] = 0.0f;
#pragma unroll 8
        for (int e = 0; e < 64; e++) {
            const float4 q  = *(const float4*)&Qs[e * SPAD + tx * 4];
            const float4 kv = *(const float4*)&Ks[e * SPAD + ty * 4];
            const float qa[4] = {q.x, q.y, q.z, q.w};
            const float ka[4] = {kv.x, kv.y, kv.z, kv.w};
#pragma unroll
            for (int i = 0; i < 4; i++)
#pragma unroll
                for (int j = 0; j < 4; j++)
                    s[i][j] += qa[i] * ka[j];
        }
#pragma unroll
        for (int jj = 0; jj < 4; jj++) {
            const float mf = mflag[koff + ty * 4 + jj];
            float4 v;
            v.x = (mf != 0.0f) ? NEGBIG : s[0][jj];
            v.y = (mf != 0.0f) ? NEGBIG : s[1][jj];
            v.z = (mf != 0.0f) ? NEGBIG : s[2][jj];
            v.w = (mf != 0.0f) ? NEGBIG : s[3][jj];
            *(float4*)&Ss[(ty * 4 + jj) * SPAD + tx * 4] = v;
        }
        __syncthreads();

        if (tid < 64) {
            const float mold = m_s[tid];
            float mx = mold;
            for (int j = 0; j < 64; j++) mx = fmaxf(mx, Ss[j * SPAD + tid]);
            const float c = __expf(mold - mx);
            float sum = 0.0f;
            for (int j = 0; j < 64; j++) {
                const float p = __expf(Ss[j * SPAD + tid] - mx);
                Ss[j * SPAD + tid] = p;
                sum += p;
            }
            l_s[tid] = l_s[tid] * c + sum;
            m_s[tid] = mx;
            corr[tid] = c;
        }
        __syncthreads();

        const float c0 = corr[tx * 4 + 0];
        const float c1 = corr[tx * 4 + 1];
        const float c2 = corr[tx * 4 + 2];
        const float c3 = corr[tx * 4 + 3];
#pragma unroll
        for (int j = 0; j < 4; j++) {
            acc[0][j] *= c0; acc[1][j] *= c1; acc[2][j] *= c2; acc[3][j] *= c3;
        }
#pragma unroll 8
        for (int kk = 0; kk < 64; kk++) {
            const float4 p = *(const float4*)&Ss[kk * SPAD + tx * 4];
            const float4 v = *(const float4*)&Vs[kk * 64 + ty * 4];
            const float pa[4] = {p.x, p.y, p.z, p.w};
            const float va[4] = {v.x, v.y, v.z, v.w};
#pragma unroll
            for (int i = 0; i < 4; i++)
#pragma unroll
                for (int j = 0; j < 4; j++)
                    acc[i][j] += pa[i] * va[j];
        }
    }

    __syncthreads();
#pragma unroll
    for (int ii = 0; ii < 4; ii++) {
        const int r = tx * 4 + ii;
        const float inv = 1.0f / l_s[r];
        const int row = qt * 64 + r;
        const size_t base = ((size_t)b * Tq + row) * Dd + h * 64 + ty * 4;
        __align__(8) __half hv[4];
#pragma unroll
        for (int j = 0; j < 4; j++)
            hv[j] = __float2half_rn(acc[ii][j] * inv);
        *(uint2*)&outh[base] = *(uint2*)hv;
    }
}

// ======================= launch =============================================
extern "C" void kernel_launch(void* const* d_in, const int* in_sizes, int n_in,
                              void* d_out, int out_size)
{
    const float* feats = (const float*)d_in[0];
    const float* inps  = (const float*)d_in[1];
    const int*   mask  = (const int*)d_in[2];
    const float* W_f  = (const float*)d_in[3];
    const float* b_f  = (const float*)d_in[4];
    const float* W_i  = (const float*)d_in[5];
    const float* b_i  = (const float*)d_in[6];
    const float* Wu_v = (const float*)d_in[7];
    const float* bu_v = (const float*)d_in[8];
    const float* Wu_l = (const float*)d_in[9];
    const float* bu_l = (const float*)d_in[10];
    float* out = (float*)d_out;

    float *pf, *pi;
    cudaGetSymbolAddress((void**)&pf, g_proj_f);
    cudaGetSymbolAddress((void**)&pi, g_proj_i);
    __half *fa, *ia, *wh, *av, *al;
    cudaGetSymbolAddress((void**)&fa, g_fa);
    cudaGetSymbolAddress((void**)&ia, g_ia);
    cudaGetSymbolAddress((void**)&wh, g_wh);
    cudaGetSymbolAddress((void**)&av, g_av);
    cudaGetSymbolAddress((void**)&al, g_al);

    const size_t SF = (size_t)Bb * T1c * Dd;  // 6291456
    const size_t SI = (size_t)Bb * T2c * Dd;  // 786432
    const size_t WSZ = (size_t)Dd * Dd;       // 589824
    const int NF = (int)SF, NI = (int)SI;

    cudaFuncSetAttribute(gemm_mma, cudaFuncAttributeMaxDynamicSharedMemorySize, GEMM_SMEM);
    const int fsm = (3 * 64 * SPAD + 64 * 64 + 3 * 64 + (T1c + T2c)) * (int)sizeof(float);
    cudaFuncSetAttribute(flash_kernel, cudaFuncAttributeMaxDynamicSharedMemorySize, fsm);

    // 3 conversion launches; launch #4 = profiled big projection gemm_mma.
    conv_f16<<<(NF + 255) / 256, 256>>>(feats, fa, NF);                         // 1
    conv_f16<<<(NI + 255) / 256, 256>>>(inps, ia, NI);                          // 2
    conv_wsplit_all<<<dim3(24, 24, 14), 256>>>(W_f, W_i, Wu_v, Wu_l, wh);       // 3

    // 4: big projection GEMM (profiled). N tile 256 -> grid.x = 3.
    gemm_mma<<<dim3(3, 64, 6), 256, GEMM_SMEM>>>(fa, wh, b_f, pf,
                                                 Bb * T1c, T1c, PROJ_SCALE, 0);
    gemm_mma<<<dim3(3, 8, 6), 256, GEMM_SMEM>>>(ia, wh + 6 * WSZ, b_i, pi,
                                                Bb * T2c, T2c, PROJ_SCALE, 0);

    // attention (writes fp16 directly)
    flash_kernel<<<dim3(8, Hh, Bb), 256, fsm>>>(
        pf + 1 * SF, pf + 3 * SF, pf + 0 * SF, pf + 2 * SF,
        pi + 0 * SI, pi + 1 * SI, mask, av, T1c);
    flash_kernel<<<dim3(1, Hh, Bb), 256, fsm>>>(
        pi + 2 * SI, pi + 3 * SI, pf + 4 * SF, pf + 5 * SF,
        pi + 4 * SI, pi + 5 * SI, mask, al, T2c);

    // output projections
    gemm_mma<<<dim3(3, 64, 1), 256, GEMM_SMEM>>>(av, wh + 12 * WSZ,
                                                 bu_v, out, Bb * T1c, T1c, 1.0f, 1);
    gemm_mma<<<dim3(3, 8, 1), 256, GEMM_SMEM>>>(al, wh + 13 * WSZ,
                                                bu_l, out + SF, Bb * T2c, T2c, 1.0f, 1);
}

// round 13
// speedup vs baseline: 1.5058x; 1.0145x over previous
#include <cuda_runtime.h>
#include <cuda_fp16.h>
#include <cstdint>
#include <math.h>

#define Hh 12
#define Dd 768
#define T1c 512
#define T2c 64
#define Bb 16
#define SPAD 68

static const float PROJ_SCALE = 0.3535533905932738f; // 64^-0.25
#define NEGBIG (-1e9f)

// ======================= PTX helpers (baseline ISA only) ====================
__device__ __forceinline__ uint32_t smem_to_u32(const void* p) {
    uint32_t a;
    asm("{ .reg .u64 t; cvta.to.shared.u64 t, %1; cvt.u32.u64 %0, t; }" : "=r"(a) : "l"(p));
    return a;
}
__device__ __forceinline__ void cp16(uint32_t saddr, const void* g) {
    asm volatile("cp.async.ca.shared.global [%0], [%1], 16;" :: "r"(saddr), "l"(g));
}
__device__ __forceinline__ void ldsm4(uint32_t* r, uint32_t addr) {
    asm volatile("ldmatrix.sync.aligned.m8n8.x4.shared.b16 {%0,%1,%2,%3}, [%4];"
        : "=r"(r[0]), "=r"(r[1]), "=r"(r[2]), "=r"(r[3]) : "r"(addr));
}
__device__ __forceinline__ void mma_f16(float* c, const uint32_t* a, const uint32_t* b) {
    asm volatile(
        "mma.sync.aligned.m16n8k16.row.col.f32.f16.f16.f32 "
        "{%0,%1,%2,%3}, {%4,%5,%6,%7}, {%8,%9}, {%0,%1,%2,%3};"
        : "+f"(c[0]), "+f"(c[1]), "+f"(c[2]), "+f"(c[3])
        : "r"(a[0]), "r"(a[1]), "r"(a[2]), "r"(a[3]), "r"(b[0]), "r"(b[1]));
}

// ======================= scratch (device globals) ===========================
__device__ float g_proj_f[6ull * Bb * T1c * Dd];   // [6][B][H][T1][64]
__device__ float g_proj_i[6ull * Bb * T2c * Dd];   // [6][B][H][T2][64]

__device__ __half g_fa[(size_t)Bb * T1c * Dd];
__device__ __half g_ia[(size_t)Bb * T2c * Dd];
// 14 weight matrices, fp16, K-major [z][N][K]: [0..5]=W_f [6..11]=W_i [12]=Wu_v [13]=Wu_l
__device__ __half g_wh[14ull * Dd * Dd];
__device__ __half g_av[(size_t)Bb * T1c * Dd];
__device__ __half g_al[(size_t)Bb * T2c * Dd];

// ======================= single merged conversion kernel ====================
// z in [0,13]: weight matrix z -> [z][N][K] fp16 (transposed, 24x24 xy tiles)
// z == 14:   feats -> fa (flat cast, grid-stride)
// z == 15:   inps  -> ia (flat cast, grid-stride)
__global__ __launch_bounds__(256) void conv_all(
    const float* __restrict__ feats, const float* __restrict__ inps,
    const float* __restrict__ W_f, const float* __restrict__ W_i,
    const float* __restrict__ Wu_v, const float* __restrict__ Wu_l,
    __half* __restrict__ fa, __half* __restrict__ ia, __half* __restrict__ bh)
{
    const int z = blockIdx.z;
    if (z >= 14) {
        const float* src = (z == 14) ? feats : inps;
        __half* dst = (z == 14) ? fa : ia;
        const int n = (z == 14) ? (Bb * T1c * Dd) : (Bb * T2c * Dd);
        const int stride = 24 * 24 * 256;
        for (int i = (blockIdx.y * 24 + blockIdx.x) * 256 + threadIdx.x; i < n; i += stride)
            dst[i] = __float2half_rn(src[i]);
        return;
    }
    __shared__ float t[32][33];
    const float* Wz;
    if (z < 6)       Wz = W_f  + (size_t)z * Dd * Dd;
    else if (z < 12) Wz = W_i  + (size_t)(z - 6) * Dd * Dd;
    else if (z == 12) Wz = Wu_v;
    else             Wz = Wu_l;
    const int k0 = blockIdx.y * 32, n0 = blockIdx.x * 32;
    const int tx = threadIdx.x & 31, ty = threadIdx.x >> 5; // 32 x 8
#pragma unroll
    for (int j = 0; j < 32; j += 8)
        t[ty + j][tx] = Wz[(size_t)(k0 + ty + j) * Dd + n0 + tx];
    __syncthreads();
#pragma unroll
    for (int j = 0; j < 32; j += 8) {
        float v = t[tx][ty + j];  // = W[k0+tx][n0+ty+j]
        size_t o = (size_t)z * Dd * Dd + (size_t)(n0 + ty + j) * Dd + k0 + tx;
        bh[o] = __float2half_rn(v);
    }
}

// ======================= mma.sync fp16 GEMM (unchanged from best) ===========
#define ROWB  80                  // 32 halfs + 8 pad = 80 bytes/row
#define TILE_A (128 * ROWB)       // 10240
#define TILE_Bb (256 * ROWB)      // 20480
#define STAGE_B (TILE_A + TILE_Bb) // 30720
#define GEMM_SMEM (2 * STAGE_B)   // 61440

__global__ __launch_bounds__(256, 1) void gemm_mma(
    const __half* __restrict__ Ah,
    const __half* __restrict__ Bh,
    const float* __restrict__ biasbase, float* __restrict__ Cbase,
    int M, int T, float scale, int mode)
{
    extern __shared__ __align__(16) char smem[];
    const uint32_t sb = smem_to_u32(smem);
    const int tid = threadIdx.x, lane = tid & 31, wid = tid >> 5;
    const int wm = wid & 1, wn = wid >> 1;          // warp tile 64m x 64n
    const int z = blockIdx.z;
    const int m0 = blockIdx.y * 128, n0 = blockIdx.x * 256;

    const __half* Asrc = Ah;
    const __half* Bsrc = Bh + (size_t)z * Dd * Dd;

    float acc[4][8][4];
#pragma unroll
    for (int a = 0; a < 4; a++)
#pragma unroll
        for (int b = 0; b < 8; b++)
#pragma unroll
            for (int c = 0; c < 4; c++) acc[a][b][c] = 0.0f;

#define LOAD_STAGE(kc, s) do {                                                \
    _Pragma("unroll")                                                         \
    for (int u_ = 0; u_ < 2; u_++) {                                          \
        const int idx_ = tid + u_ * 256;                                      \
        const int row_ = idx_ >> 2, cc_ = idx_ & 3;                           \
        cp16(sb + (s) * STAGE_B + row_ * ROWB + cc_ * 16,                     \
             Asrc + (size_t)(m0 + row_) * Dd + (kc) * 32 + cc_ * 8);          \
    }                                                                         \
    _Pragma("unroll")                                                         \
    for (int u_ = 0; u_ < 4; u_++) {                                          \
        const int idx_ = tid + u_ * 256;                                      \
        const int row_ = idx_ >> 2, cc_ = idx_ & 3;                           \
        cp16(sb + (s) * STAGE_B + TILE_A + row_ * ROWB + cc_ * 16,            \
             Bsrc + (size_t)(n0 + row_) * Dd + (kc) * 32 + cc_ * 8);          \
    }                                                                         \
    asm volatile("cp.async.commit_group;" ::: "memory");                      \
} while (0)

    LOAD_STAGE(0, 0);

    for (int i = 0; i < 24; i++) {
        const int s = i & 1;
        if (i + 1 < 24) {
            LOAD_STAGE(i + 1, s ^ 1);
            asm volatile("cp.async.wait_group 1;" ::: "memory");
        } else {
            asm volatile("cp.async.wait_group 0;" ::: "memory");
        }
        __syncthreads();

        const uint32_t st = sb + s * STAGE_B;
#pragma unroll
        for (int ks = 0; ks < 2; ks++) {
            const int kb = ks * 32;
            uint32_t b[8][2];
#pragma unroll
            for (int p = 0; p < 4; p++) {
                uint32_t r[4];
                uint32_t ab = st + TILE_A +
                              (wn * 64 + p * 16 + (lane & 15)) * ROWB +
                              ((lane >> 4) * 16) + kb;
                ldsm4(r, ab);
                b[p * 2][0] = r[0]; b[p * 2 + 1][0] = r[1];
                b[p * 2][1] = r[2]; b[p * 2 + 1][1] = r[3];
            }
            uint32_t a[4][4];
#pragma unroll
            for (int mt = 0; mt < 4; mt++) {
                const uint32_t ar = (wm * 64 + mt * 16 + (lane & 15)) * ROWB +
                                    ((lane >> 4) * 16) + kb;
                ldsm4(a[mt], st + ar);
            }
#pragma unroll
            for (int mt = 0; mt < 4; mt++)
#pragma unroll
                for (int nt = 0; nt < 8; nt++)
                    mma_f16(acc[mt][nt], a[mt], b[nt]);
        }
        __syncthreads();
    }

    const float* bias = biasbase + (size_t)z * Dd;
    float* C = Cbase + (size_t)z * M * Dd;
#pragma unroll
    for (int mt = 0; mt < 4; mt++)
#pragma unroll
        for (int nt = 0; nt < 8; nt++) {
            const int n = n0 + wn * 64 + nt * 8 + (lane & 3) * 2;
            const float2 bv = *(const float2*)&bias[n];
#pragma unroll
            for (int hf = 0; hf < 2; hf++) {
                const int m = m0 + wm * 64 + mt * 16 + (lane >> 2) + hf * 8;
                float2 v;
                v.x = scale * (acc[mt][nt][hf * 2 + 0] + bv.x);
                v.y = scale * (acc[mt][nt][hf * 2 + 1] + bv.y);
                if (mode == 0) {
                    const int b_ = m / T, t_ = m - b_ * T;
                    const int h = n >> 6, e = n & 63;
                    *(float2*)&C[((((size_t)(b_ * Hh + h)) * T + t_) << 6) + e] = v;
                } else {
                    *(float2*)&C[(size_t)m * Dd + n] = v;
                }
            }
        }
}

// ======================= flash attention (unchanged, now profiled) ==========
__global__ __launch_bounds__(256) void flash_kernel(
    const float* __restrict__ Q1,
    const float* __restrict__ Q2,
    const float* __restrict__ K1,
    const float* __restrict__ V1,
    const float* __restrict__ K2,
    const float* __restrict__ V2,
    const int* __restrict__ mask,
    __half* __restrict__ outh,
    int Tq)
{
    extern __shared__ __align__(16) float sm[];
    float* Qs   = sm;
    float* Ks   = Qs + 64 * SPAD;
    float* Vs   = Ks + 64 * SPAD;
    float* Ss   = Vs + 64 * 64;
    float* m_s  = Ss + 64 * SPAD;
    float* l_s  = m_s + 64;
    float* corr = l_s + 64;
    float* mflag = corr + 64;

    const int tid = threadIdx.x;
    const int tx = tid & 15;
    const int ty = tid >> 4;
    const int b = blockIdx.z, h = blockIdx.y, qt = blockIdx.x;

    const float* Q1p = Q1 + (((size_t)(b * Hh + h) * Tq) + qt * 64) * 64;
    const float* Q2p = Q2 + (((size_t)(b * Hh + h) * Tq) + qt * 64) * 64;
    const float* K1p = K1 + ((size_t)(b * Hh + h) * T1c) * 64;
    const float* V1p = V1 + ((size_t)(b * Hh + h) * T1c) * 64;
    const float* K2p = K2 + ((size_t)(b * Hh + h) * T2c) * 64;
    const float* V2p = V2 + ((size_t)(b * Hh + h) * T2c) * 64;

    for (int i = tid; i < 64 * 64; i += 256) {
        const int r = i >> 6, e = i & 63;
        Qs[e * SPAD + r] = Q1p[i];
    }
    for (int j = tid; j < T1c + T2c; j += 256)
        mflag[j] = (mask[b * (T1c + T2c) + j] != 0) ? 1.0f : 0.0f;
    if (tid < 64) { m_s[tid] = -1e30f; l_s[tid] = 0.0f; }

    float acc[4][4];
#pragma unroll
    for (int i = 0; i < 4; i++)
#pragma unroll
        for (int j = 0; j < 4; j++) acc[i][j] = 0.0f;

    for (int kt = 0; kt < 9; kt++) {
        const float* Kt;
        const float* Vt;
        int koff;
        if (kt < 8) { Kt = K1p + kt * 64 * 64; Vt = V1p + kt * 64 * 64; koff = kt * 64; }
        else        { Kt = K2p;               Vt = V2p;               koff = T1c; }

        __syncthreads();
        if (kt == 8) {
            for (int i = tid; i < 64 * 64; i += 256) {
                const int r = i >> 6, e = i & 63;
                Qs[e * SPAD + r] = Q2p[i];
            }
        }
        for (int i = tid; i < 64 * 64; i += 256) {
            const int j = i >> 6, e = i & 63;
            Ks[e * SPAD + j] = Kt[i];
        }
        for (int i = tid * 4; i < 64 * 64; i += 256 * 4)
            *(float4*)&Vs[i] = *(const float4*)&Vt[i];
        __syncthreads();

        float s[4][4];
#pragma unroll
        for (int i = 0; i < 4; i++)
#pragma unroll
            for (int j = 0; j < 4; j++) s[i][j] = 0.0f;
#pragma unroll 8
        for (int e = 0; e < 64; e++) {
            const float4 q  = *(const float4*)&Qs[e * SPAD + tx * 4];
            const float4 kv = *(const float4*)&Ks[e * SPAD + ty * 4];
            const float qa[4] = {q.x, q.y, q.z, q.w};
            const float ka[4] = {kv.x, kv.y, kv.z, kv.w};
#pragma unroll
            for (int i = 0; i < 4; i++)
#pragma unroll
                for (int j = 0; j < 4; j++)
                    s[i][j] += qa[i] * ka[j];
        }
#pragma unroll
        for (int jj = 0; jj < 4; jj++) {
            const float mf = mflag[koff + ty * 4 + jj];
            float4 v;
            v.x = (mf != 0.0f) ? NEGBIG : s[0][jj];
            v.y = (mf != 0.0f) ? NEGBIG : s[1][jj];
            v.z = (mf != 0.0f) ? NEGBIG : s[2][jj];
            v.w = (mf != 0.0f) ? NEGBIG : s[3][jj];
            *(float4*)&Ss[(ty * 4 + jj) * SPAD + tx * 4] = v;
        }
        __syncthreads();

        if (tid < 64) {
            const float mold = m_s[tid];
            float mx = mold;
            for (int j = 0; j < 64; j++) mx = fmaxf(mx, Ss[j * SPAD + tid]);
            const float c = __expf(mold - mx);
            float sum = 0.0f;
            for (int j = 0; j < 64; j++) {
                const float p = __expf(Ss[j * SPAD + tid] - mx);
                Ss[j * SPAD + tid] = p;
                sum += p;
            }
            l_s[tid] = l_s[tid] * c + sum;
            m_s[tid] = mx;
            corr[tid] = c;
        }
        __syncthreads();

        const float c0 = corr[tx * 4 + 0];
        const float c1 = corr[tx * 4 + 1];
        const float c2 = corr[tx * 4 + 2];
        const float c3 = corr[tx * 4 + 3];
#pragma unroll
        for (int j = 0; j < 4; j++) {
            acc[0][j] *= c0; acc[1][j] *= c1; acc[2][j] *= c2; acc[3][j] *= c3;
        }
#pragma unroll 8
        for (int kk = 0; kk < 64; kk++) {
            const float4 p = *(const float4*)&Ss[kk * SPAD + tx * 4];
            const float4 v = *(const float4*)&Vs[kk * 64 + ty * 4];
            const float pa[4] = {p.x, p.y, p.z, p.w};
            const float va[4] = {v.x, v.y, v.z, v.w};
#pragma unroll
            for (int i = 0; i < 4; i++)
#pragma unroll
                for (int j = 0; j < 4; j++)
                    acc[i][j] += pa[i] * va[j];
        }
    }

    __syncthreads();
#pragma unroll
    for (int ii = 0; ii < 4; ii++) {
        const int r = tx * 4 + ii;
        const float inv = 1.0f / l_s[r];
        const int row = qt * 64 + r;
        const size_t base = ((size_t)b * Tq + row) * Dd + h * 64 + ty * 4;
        __align__(8) __half hv[4];
#pragma unroll
        for (int j = 0; j < 4; j++)
            hv[j] = __float2half_rn(acc[ii][j] * inv);
        *(uint2*)&outh[base] = *(uint2*)hv;
    }
}

// ======================= launch =============================================
extern "C" void kernel_launch(void* const* d_in, const int* in_sizes, int n_in,
                              void* d_out, int out_size)
{
    const float* feats = (const float*)d_in[0];
    const float* inps  = (const float*)d_in[1];
    const int*   mask  = (const int*)d_in[2];
    const float* W_f  = (const float*)d_in[3];
    const float* b_f  = (const float*)d_in[4];
    const float* W_i  = (const float*)d_in[5];
    const float* b_i  = (const float*)d_in[6];
    const float* Wu_v = (const float*)d_in[7];
    const float* bu_v = (const float*)d_in[8];
    const float* Wu_l = (const float*)d_in[9];
    const float* bu_l = (const float*)d_in[10];
    float* out = (float*)d_out;

    float *pf, *pi;
    cudaGetSymbolAddress((void**)&pf, g_proj_f);
    cudaGetSymbolAddress((void**)&pi, g_proj_i);
    __half *fa, *ia, *wh, *av, *al;
    cudaGetSymbolAddress((void**)&fa, g_fa);
    cudaGetSymbolAddress((void**)&ia, g_ia);
    cudaGetSymbolAddress((void**)&wh, g_wh);
    cudaGetSymbolAddress((void**)&av, g_av);
    cudaGetSymbolAddress((void**)&al, g_al);

    const size_t SF = (size_t)Bb * T1c * Dd;  // 6291456
    const size_t SI = (size_t)Bb * T2c * Dd;  // 786432
    const size_t WSZ = (size_t)Dd * Dd;       // 589824

    cudaFuncSetAttribute(gemm_mma, cudaFuncAttributeMaxDynamicSharedMemorySize, GEMM_SMEM);
    const int fsm = (3 * 64 * SPAD + 64 * 64 + 3 * 64 + (T1c + T2c)) * (int)sizeof(float);
    cudaFuncSetAttribute(flash_kernel, cudaFuncAttributeMaxDynamicSharedMemorySize, fsm);

    // 1: single merged conversion launch (weights z=0..13, feats z=14, inps z=15)
    conv_all<<<dim3(24, 24, 16), 256>>>(feats, inps, W_f, W_i, Wu_v, Wu_l, fa, ia, wh);

    // 2, 3: projection GEMMs
    gemm_mma<<<dim3(3, 64, 6), 256, GEMM_SMEM>>>(fa, wh, b_f, pf,
                                                 Bb * T1c, T1c, PROJ_SCALE, 0);
    gemm_mma<<<dim3(3, 8, 6), 256, GEMM_SMEM>>>(ia, wh + 6 * WSZ, b_i, pi,
                                                Bb * T2c, T2c, PROJ_SCALE, 0);

    // 4: big flash (PROFILED this round — in-graph duration finally visible)
    flash_kernel<<<dim3(8, Hh, Bb), 256, fsm>>>(
        pf + 1 * SF, pf + 3 * SF, pf + 0 * SF, pf + 2 * SF,
        pi + 0 * SI, pi + 1 * SI, mask, av, T1c);
    flash_kernel<<<dim3(1, Hh, Bb), 256, fsm>>>(
        pi + 2 * SI, pi + 3 * SI, pf + 4 * SF, pf + 5 * SF,
        pi + 4 * SI, pi + 5 * SI, mask, al, T2c);

    // output projections
    gemm_mma<<<dim3(3, 64, 1), 256, GEMM_SMEM>>>(av, wh + 12 * WSZ,
                                                 bu_v, out, Bb * T1c, T1c, 1.0f, 1);
    gemm_mma<<<dim3(3, 8, 1), 256, GEMM_SMEM>>>(al, wh + 13 * WSZ,
                                                bu_l, out + SF, Bb * T2c, T2c, 1.0f, 1);
}